// round 1
// baseline (speedup 1.0000x reference)
#include <cuda_runtime.h>
#include <math.h>

#define Bb 8
#define Tt 8192
#define Dd 512
#define Mm 512
#define PD 32
#define KK (Dd + PD)      // 544
#define LC 16
#define NC (Tt / LC)      // 512

// ---- scratch (device globals; no allocation allowed) ----
__device__ float g_chunkSum[Bb * NC * Dd];   // 8 MiB
__device__ float g_chunkPre[Bb * NC * Dd];   // 8 MiB (exclusive prefix of chunk sums)
__device__ float g_X[Bb * Mm * KK];          // 8.9 MiB  (GEMM input: [mean | fourier])
__device__ float g_FF[Mm * PD];              // fourier features per beat index
__device__ int   g_s[Bb * Mm];
__device__ int   g_e[Bb * Mm];

typedef unsigned long long ull;

__device__ __forceinline__ ull ffma2(ull a, ull b, ull c) {
    ull d;
    asm("fma.rn.f32x2 %0, %1, %2, %3;" : "=l"(d) : "l"(a), "l"(b), "l"(c));
    return d;
}
__device__ __forceinline__ ull dup2(float a) {
    ull r;
    asm("mov.b64 %0, {%1, %1};" : "=l"(r) : "f"(a));
    return r;
}
__device__ __forceinline__ float2 unpk(ull v) {
    float2 f;
    asm("mov.b64 {%0, %1}, %2;" : "=f"(f.x), "=f"(f.y) : "l"(v));
    return f;
}

// ---------------- K0: fourier features (tiny) ----------------
__global__ void kFF() {
    int m = threadIdx.x;
    double pos = (double)m / (double)(Mm - 1);
    double l1000 = log(1000.0);
    #pragma unroll
    for (int j = 0; j < PD / 2; j++) {
        double f = exp(l1000 * (double)j / (double)(PD / 2 - 1));
        double a = pos * f;
        g_FF[m * PD + j] = (float)sin(a);
        g_FF[m * PD + PD / 2 + j] = (float)cos(a);
    }
}

// ---------------- KP: clamp bounds, int32/int64 autodetect ----------------
__global__ void kP(const void* __restrict__ bounds) {
    __shared__ int flag;
    int tid = threadIdx.x, b = blockIdx.x;
    if (tid == 0) flag = 0;
    __syncthreads();
    if (tid < 128) {
        const int* w = (const int*)bounds;
        if (w[2 * tid + 1] != 0) flag = 1;  // benign race: same value
    }
    __syncthreads();
    bool isI64 = (flag == 0);   // high 32-bit words all zero -> int64 storage

    int m = tid;
    long long sv, ev;
    if (isI64) {
        const long long* p = (const long long*)bounds;
        sv = p[((long long)b * Mm + m) * 2];
        ev = p[((long long)b * Mm + m) * 2 + 1];
    } else {
        const int* p = (const int*)bounds;
        sv = p[(b * Mm + m) * 2];
        ev = p[(b * Mm + m) * 2 + 1];
    }
    long long s = sv; if (s < 0) s = 0; if (s > Tt - 1) s = Tt - 1;
    long long e = ev; if (e > Tt) e = Tt; if (e < s + 1) e = s + 1;
    g_s[b * Mm + m] = (int)s;
    g_e[b * Mm + m] = (int)e;
}

// ---------------- K1: chunk sums (streams frame_emb once) ----------------
__global__ void __launch_bounds__(128) kChunk(const float* __restrict__ frame) {
    int c = blockIdx.x, b = blockIdx.y, t4 = threadIdx.x;
    const float4* f = (const float4*)frame;
    float4 acc = make_float4(0.f, 0.f, 0.f, 0.f);
    int base = (b * Tt + c * LC) * (Dd / 4) + t4;
    #pragma unroll
    for (int r = 0; r < LC; r++) {
        float4 v = f[base + r * (Dd / 4)];
        acc.x += v.x; acc.y += v.y; acc.z += v.z; acc.w += v.w;
    }
    ((float4*)g_chunkSum)[(b * NC + c) * (Dd / 4) + t4] = acc;
}

// ---------------- K2: exclusive prefix over NC chunks, one warp per (b,d4) ----------------
__global__ void __launch_bounds__(256) kScan() {
    int gw = (blockIdx.x * blockDim.x + threadIdx.x) >> 5;   // 0..1023
    int lane = threadIdx.x & 31;
    int b  = gw >> 7;        // / 128
    int d4 = gw & 127;
    const float4* cs = (const float4*)g_chunkSum;
    float4* cp = (float4*)g_chunkPre;
    const int CPL = NC / 32; // 16 chunks per lane
    int cbase = lane * CPL;

    float4 v[CPL];
    float4 s = make_float4(0.f, 0.f, 0.f, 0.f);
    #pragma unroll
    for (int j = 0; j < CPL; j++) {
        v[j] = cs[(b * NC + cbase + j) * (Dd / 4) + d4];
        s.x += v[j].x; s.y += v[j].y; s.z += v[j].z; s.w += v[j].w;
    }
    // inclusive warp scan (component-wise)
    float4 incl = s;
    #pragma unroll
    for (int off = 1; off < 32; off <<= 1) {
        float nx = __shfl_up_sync(0xffffffffu, incl.x, off);
        float ny = __shfl_up_sync(0xffffffffu, incl.y, off);
        float nz = __shfl_up_sync(0xffffffffu, incl.z, off);
        float nw = __shfl_up_sync(0xffffffffu, incl.w, off);
        if (lane >= off) { incl.x += nx; incl.y += ny; incl.z += nz; incl.w += nw; }
    }
    float4 excl;
    excl.x = __shfl_up_sync(0xffffffffu, incl.x, 1);
    excl.y = __shfl_up_sync(0xffffffffu, incl.y, 1);
    excl.z = __shfl_up_sync(0xffffffffu, incl.z, 1);
    excl.w = __shfl_up_sync(0xffffffffu, incl.w, 1);
    if (lane == 0) excl = make_float4(0.f, 0.f, 0.f, 0.f);

    float4 run = excl;
    #pragma unroll
    for (int j = 0; j < CPL; j++) {
        cp[(b * NC + cbase + j) * (Dd / 4) + d4] = run;
        run.x += v[j].x; run.y += v[j].y; run.z += v[j].z; run.w += v[j].w;
    }
}

// ---------------- K3: gather segment means + fourier into X ----------------
__global__ void __launch_bounds__(128) kGather(const float* __restrict__ frame) {
    int m = blockIdx.x, b = blockIdx.y, t4 = threadIdx.x;
    int idx = b * Mm + m;
    int s = g_s[idx], e = g_e[idx];
    int csk = s >> 4;
    int cek = e >> 4; if (cek > NC - 1) cek = NC - 1;

    const float4* f  = (const float4*)frame;
    const float4* cp = (const float4*)g_chunkPre;

    float4 accs = cp[(b * NC + csk) * (Dd / 4) + t4];
    for (int t = csk * LC; t < s; t++) {
        float4 v = f[(b * Tt + t) * (Dd / 4) + t4];
        accs.x += v.x; accs.y += v.y; accs.z += v.z; accs.w += v.w;
    }
    float4 acce = cp[(b * NC + cek) * (Dd / 4) + t4];
    for (int t = cek * LC; t < e; t++) {
        float4 v = f[(b * Tt + t) * (Dd / 4) + t4];
        acce.x += v.x; acce.y += v.y; acce.z += v.z; acce.w += v.w;
    }
    float inv = 1.f / (float)(e - s);
    float4 r = make_float4((acce.x - accs.x) * inv, (acce.y - accs.y) * inv,
                           (acce.z - accs.z) * inv, (acce.w - accs.w) * inv);
    float4* Xr = (float4*)(g_X + idx * KK);
    Xr[t4] = r;
    if (t4 < PD / 4) {
        Xr[Dd / 4 + t4] = ((const float4*)(g_FF + m * PD))[t4];
    }
}

// ---------------- K4: GEMM  out[4096,512] = X[4096,544] @ W[544,512] + bias  (fp32x2) ----------------
__global__ void __launch_bounds__(256) kGemm(const float* __restrict__ Wm,
                                             const float* __restrict__ bias,
                                             float* __restrict__ out) {
    __shared__ __align__(16) float As[16][128];
    __shared__ __align__(16) float Bs[16][128];

    int tid = threadIdx.x;
    int n0 = blockIdx.x * 128, m0 = blockIdx.y * 128;
    int tx = tid & 15, ty = tid >> 4;
    int am = tid & 127, aj = tid >> 7;   // quads 2*aj, 2*aj+1 of the 4 k-quads
    int bn4 = tid & 31, bk = tid >> 5;   // k rows bk and bk+8

    const float* Xrow = g_X + (m0 + am) * KK;

    ull acc[8][4];
    #pragma unroll
    for (int i = 0; i < 8; i++)
        #pragma unroll
        for (int j = 0; j < 4; j++) acc[i][j] = 0ull;

    // load tile 0
    float4 la0 = *(const float4*)(Xrow + (2 * aj) * 4);
    float4 la1 = *(const float4*)(Xrow + (2 * aj + 1) * 4);
    float4 lb0 = *(const float4*)(Wm + bk * Dd + n0 + bn4 * 4);
    float4 lb1 = *(const float4*)(Wm + (bk + 8) * Dd + n0 + bn4 * 4);
    {
        int q0 = 2 * aj * 4, q1 = (2 * aj + 1) * 4;
        As[q0 + 0][am] = la0.x; As[q0 + 1][am] = la0.y; As[q0 + 2][am] = la0.z; As[q0 + 3][am] = la0.w;
        As[q1 + 0][am] = la1.x; As[q1 + 1][am] = la1.y; As[q1 + 2][am] = la1.z; As[q1 + 3][am] = la1.w;
        *(float4*)&Bs[bk][bn4 * 4] = lb0;
        *(float4*)&Bs[bk + 8][bn4 * 4] = lb1;
    }
    __syncthreads();

    #pragma unroll 1
    for (int kt = 0; kt < KK / 16; kt++) {
        float4 na0, na1, nb0, nb1;
        if (kt < KK / 16 - 1) {
            int k0 = (kt + 1) * 16;
            na0 = *(const float4*)(Xrow + k0 + (2 * aj) * 4);
            na1 = *(const float4*)(Xrow + k0 + (2 * aj + 1) * 4);
            nb0 = *(const float4*)(Wm + (k0 + bk) * Dd + n0 + bn4 * 4);
            nb1 = *(const float4*)(Wm + (k0 + bk + 8) * Dd + n0 + bn4 * 4);
        }
        #pragma unroll
        for (int k = 0; k < 16; k++) {
            float4 fa0 = *(const float4*)&As[k][ty * 8];
            float4 fa1 = *(const float4*)&As[k][ty * 8 + 4];
            ull bp[4];
            bp[0] = *(const ull*)&Bs[k][tx * 8 + 0];
            bp[1] = *(const ull*)&Bs[k][tx * 8 + 2];
            bp[2] = *(const ull*)&Bs[k][tx * 8 + 4];
            bp[3] = *(const ull*)&Bs[k][tx * 8 + 6];
            ull ap[8] = {dup2(fa0.x), dup2(fa0.y), dup2(fa0.z), dup2(fa0.w),
                         dup2(fa1.x), dup2(fa1.y), dup2(fa1.z), dup2(fa1.w)};
            #pragma unroll
            for (int i = 0; i < 8; i++)
                #pragma unroll
                for (int j = 0; j < 4; j++)
                    acc[i][j] = ffma2(ap[i], bp[j], acc[i][j]);
        }
        __syncthreads();
        if (kt < KK / 16 - 1) {
            int q0 = 2 * aj * 4, q1 = (2 * aj + 1) * 4;
            As[q0 + 0][am] = na0.x; As[q0 + 1][am] = na0.y; As[q0 + 2][am] = na0.z; As[q0 + 3][am] = na0.w;
            As[q1 + 0][am] = na1.x; As[q1 + 1][am] = na1.y; As[q1 + 2][am] = na1.z; As[q1 + 3][am] = na1.w;
            *(float4*)&Bs[bk][bn4 * 4] = nb0;
            *(float4*)&Bs[bk + 8][bn4 * 4] = nb1;
            __syncthreads();
        }
    }

    float4 bi0 = *(const float4*)(bias + n0 + tx * 8);
    float4 bi1 = *(const float4*)(bias + n0 + tx * 8 + 4);
    #pragma unroll
    for (int i = 0; i < 8; i++) {
        float2 p0 = unpk(acc[i][0]), p1 = unpk(acc[i][1]);
        float2 p2 = unpk(acc[i][2]), p3 = unpk(acc[i][3]);
        float4 r0 = make_float4(p0.x + bi0.x, p0.y + bi0.y, p1.x + bi0.z, p1.y + bi0.w);
        float4 r1 = make_float4(p2.x + bi1.x, p2.y + bi1.y, p3.x + bi1.z, p3.y + bi1.w);
        float* o = out + (m0 + ty * 8 + i) * Dd + n0 + tx * 8;
        *(float4*)o = r0;
        *(float4*)(o + 4) = r1;
    }
}

extern "C" void kernel_launch(void* const* d_in, const int* in_sizes, int n_in,
                              void* d_out, int out_size) {
    const float* frame  = (const float*)d_in[0];
    const void*  bounds = d_in[1];
    const float* Wm     = (const float*)d_in[2];
    const float* bias   = (const float*)d_in[3];
    float* out = (float*)d_out;

    kFF<<<1, Mm>>>();
    kP<<<Bb, Mm>>>(bounds);
    kChunk<<<dim3(NC, Bb), 128>>>(frame);
    kScan<<<128, 256>>>();
    kGather<<<dim3(Mm, Bb), 128>>>(frame);
    kGemm<<<dim3(Dd / 128, (Bb * Mm) / 128), 256>>>(Wm, bias, out);
}

// round 3
// speedup vs baseline: 1.1252x; 1.1252x over previous
#include <cuda_runtime.h>
#include <cuda_bf16.h>
#include <math.h>
#include <stdint.h>

#define Bb 8
#define Tt 8192
#define Dd 512
#define Mm 512
#define PD 32
#define KK (Dd + PD)      // 544
#define KP2 576           // padded K (multiple of 32)
#define LC 16
#define NC (Tt / LC)      // 512

// ---- scratch (device globals; no allocation allowed) ----
__device__ float g_chunkSum[Bb * NC * Dd];
__device__ float g_chunkPre[Bb * NC * Dd];
__device__ int   g_s[Bb * Mm];
__device__ int   g_e[Bb * Mm];
__device__ __nv_bfloat16 g_FFhi[Mm * PD];
__device__ __nv_bfloat16 g_FFlo[Mm * PD];
__device__ __nv_bfloat16 g_Xhi[Bb * Mm * KP2];
__device__ __nv_bfloat16 g_Xlo[Bb * Mm * KP2];
__device__ __nv_bfloat16 g_WhiT[Dd * KP2];   // W^T [n][k]
__device__ __nv_bfloat16 g_WloT[Dd * KP2];

// ---------------- K0: fourier features hi/lo ----------------
__global__ void kFF() {
    int m = threadIdx.x;
    double pos = (double)m / (double)(Mm - 1);
    double l1000 = log(1000.0);
    #pragma unroll
    for (int j = 0; j < PD / 2; j++) {
        double f = exp(l1000 * (double)j / (double)(PD / 2 - 1));
        double a = pos * f;
        float sv = (float)sin(a), cv = (float)cos(a);
        __nv_bfloat16 sh = __float2bfloat16(sv);
        __nv_bfloat16 ch = __float2bfloat16(cv);
        g_FFhi[m * PD + j] = sh;
        g_FFhi[m * PD + PD / 2 + j] = ch;
        g_FFlo[m * PD + j] = __float2bfloat16(sv - __bfloat162float(sh));
        g_FFlo[m * PD + PD / 2 + j] = __float2bfloat16(cv - __bfloat162float(ch));
    }
}

// ---------------- KP: clamp bounds, int32/int64 autodetect ----------------
__global__ void kP(const void* __restrict__ bounds) {
    __shared__ int flag;
    int tid = threadIdx.x, b = blockIdx.x;
    if (tid == 0) flag = 0;
    __syncthreads();
    if (tid < 128) {
        const int* w = (const int*)bounds;
        if (w[2 * tid + 1] != 0) flag = 1;
    }
    __syncthreads();
    bool isI64 = (flag == 0);

    int m = tid;
    long long sv, ev;
    if (isI64) {
        const long long* p = (const long long*)bounds;
        sv = p[((long long)b * Mm + m) * 2];
        ev = p[((long long)b * Mm + m) * 2 + 1];
    } else {
        const int* p = (const int*)bounds;
        sv = p[(b * Mm + m) * 2];
        ev = p[(b * Mm + m) * 2 + 1];
    }
    long long s = sv; if (s < 0) s = 0; if (s > Tt - 1) s = Tt - 1;
    long long e = ev; if (e > Tt) e = Tt; if (e < s + 1) e = s + 1;
    g_s[b * Mm + m] = (int)s;
    g_e[b * Mm + m] = (int)e;
}

// ---------------- K1: chunk sums ----------------
__global__ void __launch_bounds__(128) kChunk(const float* __restrict__ frame) {
    int c = blockIdx.x, b = blockIdx.y, t4 = threadIdx.x;
    const float4* f = (const float4*)frame;
    float4 acc = make_float4(0.f, 0.f, 0.f, 0.f);
    int base = (b * Tt + c * LC) * (Dd / 4) + t4;
    #pragma unroll
    for (int r = 0; r < LC; r++) {
        float4 v = f[base + r * (Dd / 4)];
        acc.x += v.x; acc.y += v.y; acc.z += v.z; acc.w += v.w;
    }
    ((float4*)g_chunkSum)[(b * NC + c) * (Dd / 4) + t4] = acc;
}

// ---------------- K2: exclusive prefix over NC chunks ----------------
__global__ void __launch_bounds__(256) kScan() {
    int gw = (blockIdx.x * blockDim.x + threadIdx.x) >> 5;
    int lane = threadIdx.x & 31;
    int b  = gw >> 7;
    int d4 = gw & 127;
    const float4* cs = (const float4*)g_chunkSum;
    float4* cp = (float4*)g_chunkPre;
    const int CPL = NC / 32;
    int cbase = lane * CPL;

    float4 v[CPL];
    float4 s = make_float4(0.f, 0.f, 0.f, 0.f);
    #pragma unroll
    for (int j = 0; j < CPL; j++) {
        v[j] = cs[(b * NC + cbase + j) * (Dd / 4) + d4];
        s.x += v[j].x; s.y += v[j].y; s.z += v[j].z; s.w += v[j].w;
    }
    float4 incl = s;
    #pragma unroll
    for (int off = 1; off < 32; off <<= 1) {
        float nx = __shfl_up_sync(0xffffffffu, incl.x, off);
        float ny = __shfl_up_sync(0xffffffffu, incl.y, off);
        float nz = __shfl_up_sync(0xffffffffu, incl.z, off);
        float nw = __shfl_up_sync(0xffffffffu, incl.w, off);
        if (lane >= off) { incl.x += nx; incl.y += ny; incl.z += nz; incl.w += nw; }
    }
    float4 excl;
    excl.x = __shfl_up_sync(0xffffffffu, incl.x, 1);
    excl.y = __shfl_up_sync(0xffffffffu, incl.y, 1);
    excl.z = __shfl_up_sync(0xffffffffu, incl.z, 1);
    excl.w = __shfl_up_sync(0xffffffffu, incl.w, 1);
    if (lane == 0) excl = make_float4(0.f, 0.f, 0.f, 0.f);

    float4 run = excl;
    #pragma unroll
    for (int j = 0; j < CPL; j++) {
        cp[(b * NC + cbase + j) * (Dd / 4) + d4] = run;
        run.x += v[j].x; run.y += v[j].y; run.z += v[j].z; run.w += v[j].w;
    }
}

// ---------------- K3: gather segment means -> bf16 hi/lo directly ----------------
__global__ void __launch_bounds__(128) kGather(const float* __restrict__ frame) {
    int m = blockIdx.x, b = blockIdx.y, t4 = threadIdx.x;
    int idx = b * Mm + m;
    int s = g_s[idx], e = g_e[idx];
    int csk = s >> 4;
    int cek = e >> 4; if (cek > NC - 1) cek = NC - 1;

    const float4* f  = (const float4*)frame;
    const float4* cp = (const float4*)g_chunkPre;

    float4 accs = cp[(b * NC + csk) * (Dd / 4) + t4];
    for (int t = csk * LC; t < s; t++) {
        float4 v = f[(b * Tt + t) * (Dd / 4) + t4];
        accs.x += v.x; accs.y += v.y; accs.z += v.z; accs.w += v.w;
    }
    float4 acce = cp[(b * NC + cek) * (Dd / 4) + t4];
    for (int t = cek * LC; t < e; t++) {
        float4 v = f[(b * Tt + t) * (Dd / 4) + t4];
        acce.x += v.x; acce.y += v.y; acce.z += v.z; acce.w += v.w;
    }
    float inv = 1.f / (float)(e - s);
    float4 r = make_float4((acce.x - accs.x) * inv, (acce.y - accs.y) * inv,
                           (acce.z - accs.z) * inv, (acce.w - accs.w) * inv);
    // split to bf16 hi/lo
    __nv_bfloat16 h0 = __float2bfloat16(r.x), h1 = __float2bfloat16(r.y);
    __nv_bfloat16 h2 = __float2bfloat16(r.z), h3 = __float2bfloat16(r.w);
    uint2 hh, ll;
    hh.x = (uint32_t)__bfloat16_as_ushort(h0) | ((uint32_t)__bfloat16_as_ushort(h1) << 16);
    hh.y = (uint32_t)__bfloat16_as_ushort(h2) | ((uint32_t)__bfloat16_as_ushort(h3) << 16);
    __nv_bfloat16 l0 = __float2bfloat16(r.x - __bfloat162float(h0));
    __nv_bfloat16 l1 = __float2bfloat16(r.y - __bfloat162float(h1));
    __nv_bfloat16 l2 = __float2bfloat16(r.z - __bfloat162float(h2));
    __nv_bfloat16 l3 = __float2bfloat16(r.w - __bfloat162float(h3));
    ll.x = (uint32_t)__bfloat16_as_ushort(l0) | ((uint32_t)__bfloat16_as_ushort(l1) << 16);
    ll.y = (uint32_t)__bfloat16_as_ushort(l2) | ((uint32_t)__bfloat16_as_ushort(l3) << 16);

    *(uint2*)(g_Xhi + (size_t)idx * KP2 + 4 * t4) = hh;
    *(uint2*)(g_Xlo + (size_t)idx * KP2 + 4 * t4) = ll;

    if (t4 < 16) {
        uint2 fh = make_uint2(0u, 0u), fl = make_uint2(0u, 0u);
        if (t4 < 8) {
            fh = *(const uint2*)(g_FFhi + m * PD + 4 * t4);
            fl = *(const uint2*)(g_FFlo + m * PD + 4 * t4);
        }
        *(uint2*)(g_Xhi + (size_t)idx * KP2 + Dd + 4 * t4) = fh;
        *(uint2*)(g_Xlo + (size_t)idx * KP2 + Dd + 4 * t4) = fl;
    }
}

// ---------------- K3c: split + transpose W -> [n][k] bf16 hi/lo ----------------
__global__ void __launch_bounds__(Dd) kSplitW(const float* __restrict__ W) {
    int k = blockIdx.x, n = threadIdx.x;
    float v = (k < KK) ? W[k * Dd + n] : 0.f;
    __nv_bfloat16 h = __float2bfloat16(v);
    float rlo = v - __bfloat162float(h);
    g_WhiT[n * KP2 + k] = h;
    g_WloT[n * KP2 + k] = __float2bfloat16(rlo);
}

// ================= mma.sync bf16 GEMM =================
// out[4096,512] = X @ W + b via 3-term bf16 split.
// CTA tile 128(m) x 128(n), KT=32. 8 warps = 2(m) x 4(n); warp tile 64x32.

#define KT 32
#define SROW 40                          // padded row stride (bf16 elems)
#define TILE_E (128 * SROW)              // 5120 elems per tile
#define ST_E   (4 * TILE_E)              // stage: Ahi,Alo,Bhi,Blo
#define SM_BYTES (2 * ST_E * 2)          // 2 stages * bf16  = 81920

static __device__ __forceinline__ uint32_t smem_u32(const void* p) {
    uint32_t a;
    asm("{ .reg .u64 t; cvta.to.shared.u64 t, %1; cvt.u32.u64 %0, t; }" : "=r"(a) : "l"(p));
    return a;
}
static __device__ __forceinline__ void ldsm4(uint32_t addr, uint32_t* r) {
    asm volatile("ldmatrix.sync.aligned.m8n8.x4.shared.b16 {%0,%1,%2,%3}, [%4];"
                 : "=r"(r[0]), "=r"(r[1]), "=r"(r[2]), "=r"(r[3]) : "r"(addr));
}
static __device__ __forceinline__ void mma16816(float* c, const uint32_t* a, uint32_t b0, uint32_t b1) {
    asm volatile(
        "mma.sync.aligned.m16n8k16.row.col.f32.bf16.bf16.f32 "
        "{%0,%1,%2,%3},{%4,%5,%6,%7},{%8,%9},{%0,%1,%2,%3};"
        : "+f"(c[0]), "+f"(c[1]), "+f"(c[2]), "+f"(c[3])
        : "r"(a[0]), "r"(a[1]), "r"(a[2]), "r"(a[3]), "r"(b0), "r"(b1));
}

__global__ void __launch_bounds__(256, 1)
kGemmMMA(const float* __restrict__ bias, float* __restrict__ out) {
    extern __shared__ __align__(16) __nv_bfloat16 sm[];
    uint32_t sb = smem_u32(sm);
    int tid = threadIdx.x;
    int wid = tid >> 5, lane = tid & 31;
    int n0 = blockIdx.x * 128, m0 = blockIdx.y * 128;
    int wr = wid >> 2, wc = wid & 3;     // warp at (wr*64 m, wc*32 n)

    float acc[4][4][4];
    #pragma unroll
    for (int i = 0; i < 4; i++)
        #pragma unroll
        for (int j = 0; j < 4; j++)
            #pragma unroll
            for (int q = 0; q < 4; q++) acc[i][j][q] = 0.f;

    // gmem load helper indices: per tile 512 float4; thread does idx=tid, tid+256
    const int row0 = tid >> 2, c0 = (tid & 3) * 8;
    const int row1 = (tid + 256) >> 2, c1 = ((tid + 256) & 3) * 8;

    const __nv_bfloat16* gA_hi = g_Xhi + (size_t)(m0) * KP2;
    const __nv_bfloat16* gA_lo = g_Xlo + (size_t)(m0) * KP2;
    const __nv_bfloat16* gB_hi = g_WhiT + (size_t)(n0) * KP2;
    const __nv_bfloat16* gB_lo = g_WloT + (size_t)(n0) * KP2;

    // preload stage 0
    float4 rAh0, rAh1, rAl0, rAl1, rBh0, rBh1, rBl0, rBl1;
    {
        rAh0 = *(const float4*)(gA_hi + (size_t)row0 * KP2 + c0);
        rAh1 = *(const float4*)(gA_hi + (size_t)row1 * KP2 + c1);
        rAl0 = *(const float4*)(gA_lo + (size_t)row0 * KP2 + c0);
        rAl1 = *(const float4*)(gA_lo + (size_t)row1 * KP2 + c1);
        rBh0 = *(const float4*)(gB_hi + (size_t)row0 * KP2 + c0);
        rBh1 = *(const float4*)(gB_hi + (size_t)row1 * KP2 + c1);
        rBl0 = *(const float4*)(gB_lo + (size_t)row0 * KP2 + c0);
        rBl1 = *(const float4*)(gB_lo + (size_t)row1 * KP2 + c1);
        __nv_bfloat16* s = sm;   // stage 0
        *(float4*)(s + 0 * TILE_E + row0 * SROW + c0) = rAh0;
        *(float4*)(s + 0 * TILE_E + row1 * SROW + c1) = rAh1;
        *(float4*)(s + 1 * TILE_E + row0 * SROW + c0) = rAl0;
        *(float4*)(s + 1 * TILE_E + row1 * SROW + c1) = rAl1;
        *(float4*)(s + 2 * TILE_E + row0 * SROW + c0) = rBh0;
        *(float4*)(s + 2 * TILE_E + row1 * SROW + c1) = rBh1;
        *(float4*)(s + 3 * TILE_E + row0 * SROW + c0) = rBl0;
        *(float4*)(s + 3 * TILE_E + row1 * SROW + c1) = rBl1;
    }
    __syncthreads();

    // ldmatrix lane address pieces
    int g = lane >> 3, rIn = lane & 7;
    // A: matrices (m0-7,k0-7),(m8-15,k0-7),(m0-7,k8-15),(m8-15,k8-15)
    int aRowOff = wr * 64 + rIn + (g & 1) * 8;
    int aColOff = (g >> 1) * 8;
    // B: matrices (n0-7,k0-7),(n0-7,k8-15),(n8-15,k0-7),(n8-15,k8-15)
    int bRowOff = wc * 32 + rIn + (g >> 1) * 8;
    int bColOff = (g & 1) * 8;

    const int NSTAGE = KP2 / KT;   // 18
    #pragma unroll 1
    for (int kt = 0; kt < NSTAGE; kt++) {
        int p = kt & 1;
        // prefetch next stage to regs
        if (kt + 1 < NSTAGE) {
            int k0 = (kt + 1) * KT;
            rAh0 = *(const float4*)(gA_hi + (size_t)row0 * KP2 + k0 + c0);
            rAh1 = *(const float4*)(gA_hi + (size_t)row1 * KP2 + k0 + c1);
            rAl0 = *(const float4*)(gA_lo + (size_t)row0 * KP2 + k0 + c0);
            rAl1 = *(const float4*)(gA_lo + (size_t)row1 * KP2 + k0 + c1);
            rBh0 = *(const float4*)(gB_hi + (size_t)row0 * KP2 + k0 + c0);
            rBh1 = *(const float4*)(gB_hi + (size_t)row1 * KP2 + k0 + c1);
            rBl0 = *(const float4*)(gB_lo + (size_t)row0 * KP2 + k0 + c0);
            rBl1 = *(const float4*)(gB_lo + (size_t)row1 * KP2 + k0 + c1);
        }
        uint32_t stage = sb + (uint32_t)(p * ST_E) * 2;
        #pragma unroll
        for (int ks = 0; ks < KT / 16; ks++) {
            int k16 = ks * 16;
            uint32_t ahi[4][4], alo[4][4], bhi[2][4], blo[2][4];
            #pragma unroll
            for (int mt = 0; mt < 4; mt++) {
                uint32_t ad = stage + 2 * (0 * TILE_E + (aRowOff + mt * 16) * SROW + k16 + aColOff);
                ldsm4(ad, ahi[mt]);
                uint32_t ad2 = stage + 2 * (1 * TILE_E + (aRowOff + mt * 16) * SROW + k16 + aColOff);
                ldsm4(ad2, alo[mt]);
            }
            #pragma unroll
            for (int np = 0; np < 2; np++) {
                uint32_t bd = stage + 2 * (2 * TILE_E + (bRowOff + np * 16) * SROW + k16 + bColOff);
                ldsm4(bd, bhi[np]);
                uint32_t bd2 = stage + 2 * (3 * TILE_E + (bRowOff + np * 16) * SROW + k16 + bColOff);
                ldsm4(bd2, blo[np]);
            }
            #pragma unroll
            for (int mt = 0; mt < 4; mt++) {
                #pragma unroll
                for (int np = 0; np < 2; np++) {
                    #pragma unroll
                    for (int h = 0; h < 2; h++) {
                        int nt = np * 2 + h;
                        mma16816(acc[mt][nt], ahi[mt], bhi[np][2 * h], bhi[np][2 * h + 1]);
                        mma16816(acc[mt][nt], ahi[mt], blo[np][2 * h], blo[np][2 * h + 1]);
                        mma16816(acc[mt][nt], alo[mt], bhi[np][2 * h], bhi[np][2 * h + 1]);
                    }
                }
            }
        }
        __syncthreads();
        if (kt + 1 < NSTAGE) {
            __nv_bfloat16* s = sm + (1 - p) * ST_E;
            *(float4*)(s + 0 * TILE_E + row0 * SROW + c0) = rAh0;
            *(float4*)(s + 0 * TILE_E + row1 * SROW + c1) = rAh1;
            *(float4*)(s + 1 * TILE_E + row0 * SROW + c0) = rAl0;
            *(float4*)(s + 1 * TILE_E + row1 * SROW + c1) = rAl1;
            *(float4*)(s + 2 * TILE_E + row0 * SROW + c0) = rBh0;
            *(float4*)(s + 2 * TILE_E + row1 * SROW + c1) = rBh1;
            *(float4*)(s + 3 * TILE_E + row0 * SROW + c0) = rBl0;
            *(float4*)(s + 3 * TILE_E + row1 * SROW + c1) = rBl1;
            __syncthreads();
        }
    }

    // epilogue
    int lrow = lane >> 2, lcol2 = (lane & 3) * 2;
    #pragma unroll
    for (int mt = 0; mt < 4; mt++) {
        #pragma unroll
        for (int nt = 0; nt < 4; nt++) {
            int col = n0 + wc * 32 + nt * 8 + lcol2;
            float2 bv = *(const float2*)(bias + col);
            int r0 = m0 + wr * 64 + mt * 16 + lrow;
            float2 v0 = make_float2(acc[mt][nt][0] + bv.x, acc[mt][nt][1] + bv.y);
            float2 v1 = make_float2(acc[mt][nt][2] + bv.x, acc[mt][nt][3] + bv.y);
            *(float2*)(out + (size_t)r0 * Dd + col) = v0;
            *(float2*)(out + (size_t)(r0 + 8) * Dd + col) = v1;
        }
    }
}

extern "C" void kernel_launch(void* const* d_in, const int* in_sizes, int n_in,
                              void* d_out, int out_size) {
    const float* frame  = (const float*)d_in[0];
    const void*  bounds = d_in[1];
    const float* Wm     = (const float*)d_in[2];
    const float* bias   = (const float*)d_in[3];
    float* out = (float*)d_out;

    cudaFuncSetAttribute(kGemmMMA, cudaFuncAttributeMaxDynamicSharedMemorySize, SM_BYTES);

    kFF<<<1, Mm>>>();
    kP<<<Bb, Mm>>>(bounds);
    kSplitW<<<KP2, Dd>>>(Wm);
    kChunk<<<dim3(NC, Bb), 128>>>(frame);
    kScan<<<128, 256>>>();
    kGather<<<dim3(Mm, Bb), 128>>>(frame);
    kGemmMMA<<<dim3(Dd / 128, (Bb * Mm) / 128), 256, SM_BYTES>>>(bias, out);
}

// round 4
// speedup vs baseline: 2.5827x; 2.2954x over previous
#include <cuda_runtime.h>
#include <cuda_bf16.h>
#include <math.h>
#include <stdint.h>

#define Bb 8
#define Tt 8192
#define Dd 512
#define Mm 512
#define PD 32
#define KK (Dd + PD)      // 544
#define KP2 576           // padded K (multiple of 32)
#define LC 16
#define NC (Tt / LC)      // 512

// ---- scratch (device globals; no allocation allowed) ----
__device__ float g_chunkSum[Bb * NC * Dd];
__device__ float g_chunkPre[Bb * NC * Dd];
__device__ int   g_s[Bb * Mm];
__device__ int   g_e[Bb * Mm];
__device__ __nv_bfloat16 g_FFhi[Mm * PD];
__device__ __nv_bfloat16 g_FFlo[Mm * PD];
__device__ __nv_bfloat16 g_Xhi[Bb * Mm * KP2];
__device__ __nv_bfloat16 g_Xlo[Bb * Mm * KP2];
__device__ __nv_bfloat16 g_WhiT[Dd * KP2];   // W^T [n][k]
__device__ __nv_bfloat16 g_WloT[Dd * KP2];

// ---------------- K0: fourier features hi/lo (parallelized: 1 thread per (m,j)) ----------------
__global__ void __launch_bounds__(512) kFF() {
    int idx = blockIdx.x * blockDim.x + threadIdx.x;   // 0 .. Mm*16-1
    int m = idx >> 4, j = idx & 15;
    double pos = (double)m / (double)(Mm - 1);
    double f = exp(log(1000.0) * (double)j / (double)(PD / 2 - 1));
    double a = pos * f;
    float sv = (float)sin(a), cv = (float)cos(a);
    __nv_bfloat16 sh = __float2bfloat16(sv);
    __nv_bfloat16 ch = __float2bfloat16(cv);
    g_FFhi[m * PD + j] = sh;
    g_FFhi[m * PD + PD / 2 + j] = ch;
    g_FFlo[m * PD + j] = __float2bfloat16(sv - __bfloat162float(sh));
    g_FFlo[m * PD + PD / 2 + j] = __float2bfloat16(cv - __bfloat162float(ch));
}

// ---------------- KP: clamp bounds, int32/int64 autodetect ----------------
__global__ void kP(const void* __restrict__ bounds) {
    __shared__ int flag;
    int tid = threadIdx.x, b = blockIdx.x;
    if (tid == 0) flag = 0;
    __syncthreads();
    if (tid < 128) {
        const int* w = (const int*)bounds;
        if (w[2 * tid + 1] != 0) flag = 1;
    }
    __syncthreads();
    bool isI64 = (flag == 0);

    int m = tid;
    long long sv, ev;
    if (isI64) {
        const long long* p = (const long long*)bounds;
        sv = p[((long long)b * Mm + m) * 2];
        ev = p[((long long)b * Mm + m) * 2 + 1];
    } else {
        const int* p = (const int*)bounds;
        sv = p[(b * Mm + m) * 2];
        ev = p[(b * Mm + m) * 2 + 1];
    }
    long long s = sv; if (s < 0) s = 0; if (s > Tt - 1) s = Tt - 1;
    long long e = ev; if (e > Tt) e = Tt; if (e < s + 1) e = s + 1;
    g_s[b * Mm + m] = (int)s;
    g_e[b * Mm + m] = (int)e;
}

// ---------------- K1: chunk sums ----------------
__global__ void __launch_bounds__(128) kChunk(const float* __restrict__ frame) {
    int c = blockIdx.x, b = blockIdx.y, t4 = threadIdx.x;
    const float4* f = (const float4*)frame;
    float4 acc = make_float4(0.f, 0.f, 0.f, 0.f);
    int base = (b * Tt + c * LC) * (Dd / 4) + t4;
    #pragma unroll
    for (int r = 0; r < LC; r++) {
        float4 v = f[base + r * (Dd / 4)];
        acc.x += v.x; acc.y += v.y; acc.z += v.z; acc.w += v.w;
    }
    ((float4*)g_chunkSum)[(b * NC + c) * (Dd / 4) + t4] = acc;
}

// ---------------- K2: exclusive prefix over NC chunks ----------------
__global__ void __launch_bounds__(256) kScan() {
    int gw = (blockIdx.x * blockDim.x + threadIdx.x) >> 5;
    int lane = threadIdx.x & 31;
    int b  = gw >> 7;
    int d4 = gw & 127;
    const float4* cs = (const float4*)g_chunkSum;
    float4* cp = (float4*)g_chunkPre;
    const int CPL = NC / 32;
    int cbase = lane * CPL;

    float4 v[CPL];
    float4 s = make_float4(0.f, 0.f, 0.f, 0.f);
    #pragma unroll
    for (int j = 0; j < CPL; j++) {
        v[j] = cs[(b * NC + cbase + j) * (Dd / 4) + d4];
        s.x += v[j].x; s.y += v[j].y; s.z += v[j].z; s.w += v[j].w;
    }
    float4 incl = s;
    #pragma unroll
    for (int off = 1; off < 32; off <<= 1) {
        float nx = __shfl_up_sync(0xffffffffu, incl.x, off);
        float ny = __shfl_up_sync(0xffffffffu, incl.y, off);
        float nz = __shfl_up_sync(0xffffffffu, incl.z, off);
        float nw = __shfl_up_sync(0xffffffffu, incl.w, off);
        if (lane >= off) { incl.x += nx; incl.y += ny; incl.z += nz; incl.w += nw; }
    }
    float4 excl;
    excl.x = __shfl_up_sync(0xffffffffu, incl.x, 1);
    excl.y = __shfl_up_sync(0xffffffffu, incl.y, 1);
    excl.z = __shfl_up_sync(0xffffffffu, incl.z, 1);
    excl.w = __shfl_up_sync(0xffffffffu, incl.w, 1);
    if (lane == 0) excl = make_float4(0.f, 0.f, 0.f, 0.f);

    float4 run = excl;
    #pragma unroll
    for (int j = 0; j < CPL; j++) {
        cp[(b * NC + cbase + j) * (Dd / 4) + d4] = run;
        run.x += v[j].x; run.y += v[j].y; run.z += v[j].z; run.w += v[j].w;
    }
}

// ---------------- K3: gather segment means -> bf16 hi/lo directly ----------------
__global__ void __launch_bounds__(128) kGather(const float* __restrict__ frame) {
    int m = blockIdx.x, b = blockIdx.y, t4 = threadIdx.x;
    int idx = b * Mm + m;
    int s = g_s[idx], e = g_e[idx];
    int csk = s >> 4;
    int cek = e >> 4; if (cek > NC - 1) cek = NC - 1;

    const float4* f  = (const float4*)frame;
    const float4* cp = (const float4*)g_chunkPre;

    float4 accs = cp[(b * NC + csk) * (Dd / 4) + t4];
    for (int t = csk * LC; t < s; t++) {
        float4 v = f[(b * Tt + t) * (Dd / 4) + t4];
        accs.x += v.x; accs.y += v.y; accs.z += v.z; accs.w += v.w;
    }
    float4 acce = cp[(b * NC + cek) * (Dd / 4) + t4];
    for (int t = cek * LC; t < e; t++) {
        float4 v = f[(b * Tt + t) * (Dd / 4) + t4];
        acce.x += v.x; acce.y += v.y; acce.z += v.z; acce.w += v.w;
    }
    float inv = 1.f / (float)(e - s);
    float4 r = make_float4((acce.x - accs.x) * inv, (acce.y - accs.y) * inv,
                           (acce.z - accs.z) * inv, (acce.w - accs.w) * inv);
    // split to bf16 hi/lo
    __nv_bfloat16 h0 = __float2bfloat16(r.x), h1 = __float2bfloat16(r.y);
    __nv_bfloat16 h2 = __float2bfloat16(r.z), h3 = __float2bfloat16(r.w);
    uint2 hh, ll;
    hh.x = (uint32_t)__bfloat16_as_ushort(h0) | ((uint32_t)__bfloat16_as_ushort(h1) << 16);
    hh.y = (uint32_t)__bfloat16_as_ushort(h2) | ((uint32_t)__bfloat16_as_ushort(h3) << 16);
    __nv_bfloat16 l0 = __float2bfloat16(r.x - __bfloat162float(h0));
    __nv_bfloat16 l1 = __float2bfloat16(r.y - __bfloat162float(h1));
    __nv_bfloat16 l2 = __float2bfloat16(r.z - __bfloat162float(h2));
    __nv_bfloat16 l3 = __float2bfloat16(r.w - __bfloat162float(h3));
    ll.x = (uint32_t)__bfloat16_as_ushort(l0) | ((uint32_t)__bfloat16_as_ushort(l1) << 16);
    ll.y = (uint32_t)__bfloat16_as_ushort(l2) | ((uint32_t)__bfloat16_as_ushort(l3) << 16);

    *(uint2*)(g_Xhi + (size_t)idx * KP2 + 4 * t4) = hh;
    *(uint2*)(g_Xlo + (size_t)idx * KP2 + 4 * t4) = ll;

    if (t4 < 16) {
        uint2 fh = make_uint2(0u, 0u), fl = make_uint2(0u, 0u);
        if (t4 < 8) {
            fh = *(const uint2*)(g_FFhi + m * PD + 4 * t4);
            fl = *(const uint2*)(g_FFlo + m * PD + 4 * t4);
        }
        *(uint2*)(g_Xhi + (size_t)idx * KP2 + Dd + 4 * t4) = fh;
        *(uint2*)(g_Xlo + (size_t)idx * KP2 + Dd + 4 * t4) = fl;
    }
}

// ---------------- K3c: split + transpose W -> [n][k] bf16 hi/lo ----------------
__global__ void __launch_bounds__(Dd) kSplitW(const float* __restrict__ W) {
    int k = blockIdx.x, n = threadIdx.x;
    float v = (k < KK) ? W[k * Dd + n] : 0.f;
    __nv_bfloat16 h = __float2bfloat16(v);
    float rlo = v - __bfloat162float(h);
    g_WhiT[n * KP2 + k] = h;
    g_WloT[n * KP2 + k] = __float2bfloat16(rlo);
}

// ================= mma.sync bf16 GEMM =================
// out[4096,512] = X @ W + b via 3-term bf16 split.
// CTA tile 128(m) x 128(n), KT=32. 8 warps = 2(m) x 4(n); warp tile 64x32.

#define KT 32
#define SROW 40                          // padded row stride (bf16 elems)
#define TILE_E (128 * SROW)              // 5120 elems per tile
#define ST_E   (4 * TILE_E)              // stage: Ahi,Alo,Bhi,Blo
#define SM_BYTES (2 * ST_E * 2)          // 2 stages * bf16  = 81920

static __device__ __forceinline__ uint32_t smem_u32(const void* p) {
    uint32_t a;
    asm("{ .reg .u64 t; cvta.to.shared.u64 t, %1; cvt.u32.u64 %0, t; }" : "=r"(a) : "l"(p));
    return a;
}
static __device__ __forceinline__ void ldsm4(uint32_t addr, uint32_t* r) {
    asm volatile("ldmatrix.sync.aligned.m8n8.x4.shared.b16 {%0,%1,%2,%3}, [%4];"
                 : "=r"(r[0]), "=r"(r[1]), "=r"(r[2]), "=r"(r[3]) : "r"(addr));
}
static __device__ __forceinline__ void mma16816(float* c, const uint32_t* a, uint32_t b0, uint32_t b1) {
    asm volatile(
        "mma.sync.aligned.m16n8k16.row.col.f32.bf16.bf16.f32 "
        "{%0,%1,%2,%3},{%4,%5,%6,%7},{%8,%9},{%0,%1,%2,%3};"
        : "+f"(c[0]), "+f"(c[1]), "+f"(c[2]), "+f"(c[3])
        : "r"(a[0]), "r"(a[1]), "r"(a[2]), "r"(a[3]), "r"(b0), "r"(b1));
}

__global__ void __launch_bounds__(256, 1)
kGemmMMA(const float* __restrict__ bias, float* __restrict__ out) {
    extern __shared__ __align__(16) __nv_bfloat16 sm[];
    uint32_t sb = smem_u32(sm);
    int tid = threadIdx.x;
    int wid = tid >> 5, lane = tid & 31;
    int n0 = blockIdx.x * 128, m0 = blockIdx.y * 128;
    int wr = wid >> 2, wc = wid & 3;     // warp at (wr*64 m, wc*32 n)

    float acc[4][4][4];
    #pragma unroll
    for (int i = 0; i < 4; i++)
        #pragma unroll
        for (int j = 0; j < 4; j++)
            #pragma unroll
            for (int q = 0; q < 4; q++) acc[i][j][q] = 0.f;

    // gmem load helper indices: per tile 512 float4; thread does idx=tid, tid+256
    const int row0 = tid >> 2, c0 = (tid & 3) * 8;
    const int row1 = (tid + 256) >> 2, c1 = ((tid + 256) & 3) * 8;

    const __nv_bfloat16* gA_hi = g_Xhi + (size_t)(m0) * KP2;
    const __nv_bfloat16* gA_lo = g_Xlo + (size_t)(m0) * KP2;
    const __nv_bfloat16* gB_hi = g_WhiT + (size_t)(n0) * KP2;
    const __nv_bfloat16* gB_lo = g_WloT + (size_t)(n0) * KP2;

    // preload stage 0
    float4 rAh0, rAh1, rAl0, rAl1, rBh0, rBh1, rBl0, rBl1;
    {
        rAh0 = *(const float4*)(gA_hi + (size_t)row0 * KP2 + c0);
        rAh1 = *(const float4*)(gA_hi + (size_t)row1 * KP2 + c1);
        rAl0 = *(const float4*)(gA_lo + (size_t)row0 * KP2 + c0);
        rAl1 = *(const float4*)(gA_lo + (size_t)row1 * KP2 + c1);
        rBh0 = *(const float4*)(gB_hi + (size_t)row0 * KP2 + c0);
        rBh1 = *(const float4*)(gB_hi + (size_t)row1 * KP2 + c1);
        rBl0 = *(const float4*)(gB_lo + (size_t)row0 * KP2 + c0);
        rBl1 = *(const float4*)(gB_lo + (size_t)row1 * KP2 + c1);
        __nv_bfloat16* s = sm;   // stage 0
        *(float4*)(s + 0 * TILE_E + row0 * SROW + c0) = rAh0;
        *(float4*)(s + 0 * TILE_E + row1 * SROW + c1) = rAh1;
        *(float4*)(s + 1 * TILE_E + row0 * SROW + c0) = rAl0;
        *(float4*)(s + 1 * TILE_E + row1 * SROW + c1) = rAl1;
        *(float4*)(s + 2 * TILE_E + row0 * SROW + c0) = rBh0;
        *(float4*)(s + 2 * TILE_E + row1 * SROW + c1) = rBh1;
        *(float4*)(s + 3 * TILE_E + row0 * SROW + c0) = rBl0;
        *(float4*)(s + 3 * TILE_E + row1 * SROW + c1) = rBl1;
    }
    __syncthreads();

    // ldmatrix lane address pieces
    int g = lane >> 3, rIn = lane & 7;
    // A: matrices (m0-7,k0-7),(m8-15,k0-7),(m0-7,k8-15),(m8-15,k8-15)
    int aRowOff = wr * 64 + rIn + (g & 1) * 8;
    int aColOff = (g >> 1) * 8;
    // B: matrices (n0-7,k0-7),(n0-7,k8-15),(n8-15,k0-7),(n8-15,k8-15)
    int bRowOff = wc * 32 + rIn + (g >> 1) * 8;
    int bColOff = (g & 1) * 8;

    const int NSTAGE = KP2 / KT;   // 18
    #pragma unroll 1
    for (int kt = 0; kt < NSTAGE; kt++) {
        int p = kt & 1;
        // prefetch next stage to regs
        if (kt + 1 < NSTAGE) {
            int k0 = (kt + 1) * KT;
            rAh0 = *(const float4*)(gA_hi + (size_t)row0 * KP2 + k0 + c0);
            rAh1 = *(const float4*)(gA_hi + (size_t)row1 * KP2 + k0 + c1);
            rAl0 = *(const float4*)(gA_lo + (size_t)row0 * KP2 + k0 + c0);
            rAl1 = *(const float4*)(gA_lo + (size_t)row1 * KP2 + k0 + c1);
            rBh0 = *(const float4*)(gB_hi + (size_t)row0 * KP2 + k0 + c0);
            rBh1 = *(const float4*)(gB_hi + (size_t)row1 * KP2 + k0 + c1);
            rBl0 = *(const float4*)(gB_lo + (size_t)row0 * KP2 + k0 + c0);
            rBl1 = *(const float4*)(gB_lo + (size_t)row1 * KP2 + k0 + c1);
        }
        uint32_t stage = sb + (uint32_t)(p * ST_E) * 2;
        #pragma unroll
        for (int ks = 0; ks < KT / 16; ks++) {
            int k16 = ks * 16;
            uint32_t ahi[4][4], alo[4][4], bhi[2][4], blo[2][4];
            #pragma unroll
            for (int mt = 0; mt < 4; mt++) {
                uint32_t ad = stage + 2 * (0 * TILE_E + (aRowOff + mt * 16) * SROW + k16 + aColOff);
                ldsm4(ad, ahi[mt]);
                uint32_t ad2 = stage + 2 * (1 * TILE_E + (aRowOff + mt * 16) * SROW + k16 + aColOff);
                ldsm4(ad2, alo[mt]);
            }
            #pragma unroll
            for (int np = 0; np < 2; np++) {
                uint32_t bd = stage + 2 * (2 * TILE_E + (bRowOff + np * 16) * SROW + k16 + bColOff);
                ldsm4(bd, bhi[np]);
                uint32_t bd2 = stage + 2 * (3 * TILE_E + (bRowOff + np * 16) * SROW + k16 + bColOff);
                ldsm4(bd2, blo[np]);
            }
            #pragma unroll
            for (int mt = 0; mt < 4; mt++) {
                #pragma unroll
                for (int np = 0; np < 2; np++) {
                    #pragma unroll
                    for (int h = 0; h < 2; h++) {
                        int nt = np * 2 + h;
                        mma16816(acc[mt][nt], ahi[mt], bhi[np][2 * h], bhi[np][2 * h + 1]);
                        mma16816(acc[mt][nt], ahi[mt], blo[np][2 * h], blo[np][2 * h + 1]);
                        mma16816(acc[mt][nt], alo[mt], bhi[np][2 * h], bhi[np][2 * h + 1]);
                    }
                }
            }
        }
        __syncthreads();
        if (kt + 1 < NSTAGE) {
            __nv_bfloat16* s = sm + (1 - p) * ST_E;
            *(float4*)(s + 0 * TILE_E + row0 * SROW + c0) = rAh0;
            *(float4*)(s + 0 * TILE_E + row1 * SROW + c1) = rAh1;
            *(float4*)(s + 1 * TILE_E + row0 * SROW + c0) = rAl0;
            *(float4*)(s + 1 * TILE_E + row1 * SROW + c1) = rAl1;
            *(float4*)(s + 2 * TILE_E + row0 * SROW + c0) = rBh0;
            *(float4*)(s + 2 * TILE_E + row1 * SROW + c1) = rBh1;
            *(float4*)(s + 3 * TILE_E + row0 * SROW + c0) = rBl0;
            *(float4*)(s + 3 * TILE_E + row1 * SROW + c1) = rBl1;
            __syncthreads();
        }
    }

    // epilogue
    int lrow = lane >> 2, lcol2 = (lane & 3) * 2;
    #pragma unroll
    for (int mt = 0; mt < 4; mt++) {
        #pragma unroll
        for (int nt = 0; nt < 4; nt++) {
            int col = n0 + wc * 32 + nt * 8 + lcol2;
            float2 bv = *(const float2*)(bias + col);
            int r0 = m0 + wr * 64 + mt * 16 + lrow;
            float2 v0 = make_float2(acc[mt][nt][0] + bv.x, acc[mt][nt][1] + bv.y);
            float2 v1 = make_float2(acc[mt][nt][2] + bv.x, acc[mt][nt][3] + bv.y);
            *(float2*)(out + (size_t)r0 * Dd + col) = v0;
            *(float2*)(out + (size_t)(r0 + 8) * Dd + col) = v1;
        }
    }
}

extern "C" void kernel_launch(void* const* d_in, const int* in_sizes, int n_in,
                              void* d_out, int out_size) {
    const float* frame  = (const float*)d_in[0];
    const void*  bounds = d_in[1];
    const float* Wm     = (const float*)d_in[2];
    const float* bias   = (const float*)d_in[3];
    float* out = (float*)d_out;

    cudaFuncSetAttribute(kGemmMMA, cudaFuncAttributeMaxDynamicSharedMemorySize, SM_BYTES);

    kFF<<<(Mm * 16) / 512, 512>>>();
    kP<<<Bb, Mm>>>(bounds);
    kSplitW<<<KP2, Dd>>>(Wm);
    kChunk<<<dim3(NC, Bb), 128>>>(frame);
    kScan<<<128, 256>>>();
    kGather<<<dim3(Mm, Bb), 128>>>(frame);
    kGemmMMA<<<dim3(Dd / 128, (Bb * Mm) / 128), 256, SM_BYTES>>>(bias, out);
}

// round 8
// speedup vs baseline: 2.8336x; 1.0971x over previous
#include <cuda_runtime.h>
#include <cuda_bf16.h>
#include <math.h>
#include <stdint.h>

#define Bb 8
#define Tt 8192
#define Dd 512
#define Mm 512
#define PD 32
#define KK (Dd + PD)      // 544
#define KP2 576           // padded K (multiple of 32)
#define LC 16
#define NC (Tt / LC)      // 512

// ---- scratch (device globals; no allocation allowed) ----
__device__ float g_chunkSum[Bb * NC * Dd];            // 8 MB
__device__ float g_chunkPre[Bb * NC * Dd];            // 8 MB
__device__ float g_fine[Bb * NC * 3 * Dd];            // 25 MB: partial sums of 4/8/12 rows
__device__ int   g_s[Bb * Mm];
__device__ int   g_e[Bb * Mm];
__device__ __nv_bfloat16 g_FFhi[Mm * PD];
__device__ __nv_bfloat16 g_FFlo[Mm * PD];
__device__ __nv_bfloat16 g_Xhi[Bb * Mm * KP2];
__device__ __nv_bfloat16 g_Xlo[Bb * Mm * KP2];
__device__ __nv_bfloat16 g_WhiT[Dd * KP2];   // W^T [n][k]
__device__ __nv_bfloat16 g_WloT[Dd * KP2];

// ---------------- kPrep: fused kP (blocks 0-7) + kFF (8-23) + kSplitW (24-599) ----------------
__global__ void __launch_bounds__(512) kPrep(const void* __restrict__ bounds,
                                             const float* __restrict__ W) {
    int blk = blockIdx.x, tid = threadIdx.x;
    if (blk < 8) {
        // --- clamp bounds, int32/int64 autodetect ---
        __shared__ int flag;
        int b = blk;
        if (tid == 0) flag = 0;
        __syncthreads();
        if (tid < 128) {
            const int* w = (const int*)bounds;
            if (w[2 * tid + 1] != 0) flag = 1;
        }
        __syncthreads();
        bool isI64 = (flag == 0);
        int m = tid;
        long long sv, ev;
        if (isI64) {
            const long long* p = (const long long*)bounds;
            sv = p[((long long)b * Mm + m) * 2];
            ev = p[((long long)b * Mm + m) * 2 + 1];
        } else {
            const int* p = (const int*)bounds;
            sv = p[(b * Mm + m) * 2];
            ev = p[(b * Mm + m) * 2 + 1];
        }
        long long s = sv; if (s < 0) s = 0; if (s > Tt - 1) s = Tt - 1;
        long long e = ev; if (e > Tt) e = Tt; if (e < s + 1) e = s + 1;
        g_s[b * Mm + m] = (int)s;
        g_e[b * Mm + m] = (int)e;
    } else if (blk < 24) {
        // --- fourier features hi/lo: 1 thread per (m, j) ---
        int idx = (blk - 8) * 512 + tid;    // 0 .. 8191
        int m = idx >> 4, j = idx & 15;
        double pos = (double)m / (double)(Mm - 1);
        double f = exp(log(1000.0) * (double)j / (double)(PD / 2 - 1));
        double a = pos * f;
        float sv = (float)sin(a), cv = (float)cos(a);
        __nv_bfloat16 sh = __float2bfloat16(sv);
        __nv_bfloat16 ch = __float2bfloat16(cv);
        g_FFhi[m * PD + j] = sh;
        g_FFhi[m * PD + PD / 2 + j] = ch;
        g_FFlo[m * PD + j] = __float2bfloat16(sv - __bfloat162float(sh));
        g_FFlo[m * PD + PD / 2 + j] = __float2bfloat16(cv - __bfloat162float(ch));
    } else {
        // --- split + transpose W -> [n][k] bf16 hi/lo ---
        int k = blk - 24, n = tid;          // k in [0, 576)
        float v = (k < KK) ? W[k * Dd + n] : 0.f;
        __nv_bfloat16 h = __float2bfloat16(v);
        float rlo = v - __bfloat162float(h);
        g_WhiT[n * KP2 + k] = h;
        g_WloT[n * KP2 + k] = __float2bfloat16(rlo);
    }
}

// ---------------- K1: chunk sums + fine partials (4/8/12 rows) ----------------
__global__ void __launch_bounds__(128) kChunk(const float* __restrict__ frame) {
    int c = blockIdx.x, b = blockIdx.y, t4 = threadIdx.x;
    const float4* f = (const float4*)frame;
    float4* fine = (float4*)g_fine;
    float4 acc = make_float4(0.f, 0.f, 0.f, 0.f);
    int base = (b * Tt + c * LC) * (Dd / 4) + t4;
    size_t fbase = ((size_t)(b * NC + c) * 3) * (Dd / 4) + t4;
    #pragma unroll
    for (int r = 0; r < LC; r++) {
        float4 v = f[base + r * (Dd / 4)];
        acc.x += v.x; acc.y += v.y; acc.z += v.z; acc.w += v.w;
        if (r == 3)  fine[fbase + 0 * (Dd / 4)] = acc;
        if (r == 7)  fine[fbase + 1 * (Dd / 4)] = acc;
        if (r == 11) fine[fbase + 2 * (Dd / 4)] = acc;
    }
    ((float4*)g_chunkSum)[(b * NC + c) * (Dd / 4) + t4] = acc;
}

// ---------------- K2: exclusive prefix over NC chunks (hierarchical, 4 warps/block) ----------------
__global__ void __launch_bounds__(128) kScan() {
    int d4 = blockIdx.x, b = blockIdx.y;
    int tid = threadIdx.x, wid = tid >> 5, lane = tid & 31;
    __shared__ float4 wtot[4];

    const float4* cs = (const float4*)g_chunkSum;
    float4* cp = (float4*)g_chunkPre;
    const int CPL = 4;                        // chunks per lane
    int cbase = (wid * 32 + lane) * CPL;

    float4 v[CPL];
    float4 s = make_float4(0.f, 0.f, 0.f, 0.f);
    #pragma unroll
    for (int j = 0; j < CPL; j++) {
        v[j] = cs[(b * NC + cbase + j) * (Dd / 4) + d4];
        s.x += v[j].x; s.y += v[j].y; s.z += v[j].z; s.w += v[j].w;
    }
    float4 incl = s;
    #pragma unroll
    for (int off = 1; off < 32; off <<= 1) {
        float nx = __shfl_up_sync(0xffffffffu, incl.x, off);
        float ny = __shfl_up_sync(0xffffffffu, incl.y, off);
        float nz = __shfl_up_sync(0xffffffffu, incl.z, off);
        float nw = __shfl_up_sync(0xffffffffu, incl.w, off);
        if (lane >= off) { incl.x += nx; incl.y += ny; incl.z += nz; incl.w += nw; }
    }
    if (lane == 31) wtot[wid] = incl;
    __syncthreads();
    float4 wpre = make_float4(0.f, 0.f, 0.f, 0.f);
    #pragma unroll
    for (int w = 0; w < 4; w++) {
        if (w < wid) {
            float4 t = wtot[w];
            wpre.x += t.x; wpre.y += t.y; wpre.z += t.z; wpre.w += t.w;
        }
    }
    // exclusive across lanes: incl - s + warp prefix
    float4 run = make_float4(wpre.x + incl.x - s.x, wpre.y + incl.y - s.y,
                             wpre.z + incl.z - s.z, wpre.w + incl.w - s.w);
    #pragma unroll
    for (int j = 0; j < CPL; j++) {
        cp[(b * NC + cbase + j) * (Dd / 4) + d4] = run;
        run.x += v[j].x; run.y += v[j].y; run.z += v[j].z; run.w += v[j].w;
    }
}

// ---------------- K3: gather segment means -> bf16 hi/lo (2-level prefix) ----------------
__global__ void __launch_bounds__(128) kGather(const float* __restrict__ frame) {
    int m = blockIdx.x, b = blockIdx.y, t4 = threadIdx.x;
    int idx = b * Mm + m;
    int s = g_s[idx], e = g_e[idx];
    int csk = s >> 4;
    int cek = e >> 4; if (cek > NC - 1) cek = NC - 1;

    const float4* f  = (const float4*)frame;
    const float4* cp = (const float4*)g_chunkPre;
    const float4* fine = (const float4*)g_fine;

    // start endpoint
    float4 accs = cp[(b * NC + csk) * (Dd / 4) + t4];
    int fs = (s - csk * LC) >> 2;            // 0..3
    if (fs > 0) {
        float4 fv = fine[((size_t)(b * NC + csk) * 3 + (fs - 1)) * (Dd / 4) + t4];
        accs.x += fv.x; accs.y += fv.y; accs.z += fv.z; accs.w += fv.w;
    }
    for (int t = csk * LC + 4 * fs; t < s; t++) {
        float4 v = f[(b * Tt + t) * (Dd / 4) + t4];
        accs.x += v.x; accs.y += v.y; accs.z += v.z; accs.w += v.w;
    }
    // end endpoint
    float4 acce = cp[(b * NC + cek) * (Dd / 4) + t4];
    int de = e - cek * LC;                   // 1..16
    int fe = de >> 2; if (fe > 3) fe = 3;    // 0..3
    if (fe > 0) {
        float4 fv = fine[((size_t)(b * NC + cek) * 3 + (fe - 1)) * (Dd / 4) + t4];
        acce.x += fv.x; acce.y += fv.y; acce.z += fv.z; acce.w += fv.w;
    }
    for (int t = cek * LC + 4 * fe; t < e; t++) {
        float4 v = f[(b * Tt + t) * (Dd / 4) + t4];
        acce.x += v.x; acce.y += v.y; acce.z += v.z; acce.w += v.w;
    }

    float inv = 1.f / (float)(e - s);
    float4 r = make_float4((acce.x - accs.x) * inv, (acce.y - accs.y) * inv,
                           (acce.z - accs.z) * inv, (acce.w - accs.w) * inv);
    // split to bf16 hi/lo
    __nv_bfloat16 h0 = __float2bfloat16(r.x), h1 = __float2bfloat16(r.y);
    __nv_bfloat16 h2 = __float2bfloat16(r.z), h3 = __float2bfloat16(r.w);
    uint2 hh, ll;
    hh.x = (uint32_t)__bfloat16_as_ushort(h0) | ((uint32_t)__bfloat16_as_ushort(h1) << 16);
    hh.y = (uint32_t)__bfloat16_as_ushort(h2) | ((uint32_t)__bfloat16_as_ushort(h3) << 16);
    __nv_bfloat16 l0 = __float2bfloat16(r.x - __bfloat162float(h0));
    __nv_bfloat16 l1 = __float2bfloat16(r.y - __bfloat162float(h1));
    __nv_bfloat16 l2 = __float2bfloat16(r.z - __bfloat162float(h2));
    __nv_bfloat16 l3 = __float2bfloat16(r.w - __bfloat162float(h3));
    ll.x = (uint32_t)__bfloat16_as_ushort(l0) | ((uint32_t)__bfloat16_as_ushort(l1) << 16);
    ll.y = (uint32_t)__bfloat16_as_ushort(l2) | ((uint32_t)__bfloat16_as_ushort(l3) << 16);

    *(uint2*)(g_Xhi + (size_t)idx * KP2 + 4 * t4) = hh;
    *(uint2*)(g_Xlo + (size_t)idx * KP2 + 4 * t4) = ll;

    if (t4 < 16) {
        uint2 fh = make_uint2(0u, 0u), fl = make_uint2(0u, 0u);
        if (t4 < 8) {
            fh = *(const uint2*)(g_FFhi + m * PD + 4 * t4);
            fl = *(const uint2*)(g_FFlo + m * PD + 4 * t4);
        }
        *(uint2*)(g_Xhi + (size_t)idx * KP2 + Dd + 4 * t4) = fh;
        *(uint2*)(g_Xlo + (size_t)idx * KP2 + Dd + 4 * t4) = fl;
    }
}

// ================= mma.sync bf16 GEMM =================
// out[4096,512] = X @ W + b via 3-term bf16 split.
// CTA tile 128(m) x 128(n), KT=32. 8 warps = 2(m) x 4(n); warp tile 64x32.

#define KT 32
#define SROW 40
#define TILE_E (128 * SROW)
#define ST_E   (4 * TILE_E)
#define SM_BYTES (2 * ST_E * 2)          // 81920

static __device__ __forceinline__ uint32_t smem_u32(const void* p) {
    uint32_t a;
    asm("{ .reg .u64 t; cvta.to.shared.u64 t, %1; cvt.u32.u64 %0, t; }" : "=r"(a) : "l"(p));
    return a;
}
static __device__ __forceinline__ void ldsm4(uint32_t addr, uint32_t* r) {
    asm volatile("ldmatrix.sync.aligned.m8n8.x4.shared.b16 {%0,%1,%2,%3}, [%4];"
                 : "=r"(r[0]), "=r"(r[1]), "=r"(r[2]), "=r"(r[3]) : "r"(addr));
}
static __device__ __forceinline__ void mma16816(float* c, const uint32_t* a, uint32_t b0, uint32_t b1) {
    asm volatile(
        "mma.sync.aligned.m16n8k16.row.col.f32.bf16.bf16.f32 "
        "{%0,%1,%2,%3},{%4,%5,%6,%7},{%8,%9},{%0,%1,%2,%3};"
        : "+f"(c[0]), "+f"(c[1]), "+f"(c[2]), "+f"(c[3])
        : "r"(a[0]), "r"(a[1]), "r"(a[2]), "r"(a[3]), "r"(b0), "r"(b1));
}

__global__ void __launch_bounds__(256, 1)
kGemmMMA(const float* __restrict__ bias, float* __restrict__ out) {
    extern __shared__ __align__(16) __nv_bfloat16 sm[];
    uint32_t sb = smem_u32(sm);
    int tid = threadIdx.x;
    int wid = tid >> 5, lane = tid & 31;
    int n0 = blockIdx.x * 128, m0 = blockIdx.y * 128;
    int wr = wid >> 2, wc = wid & 3;

    float acc[4][4][4];
    #pragma unroll
    for (int i = 0; i < 4; i++)
        #pragma unroll
        for (int j = 0; j < 4; j++)
            #pragma unroll
            for (int q = 0; q < 4; q++) acc[i][j][q] = 0.f;

    const int row0 = tid >> 2, c0 = (tid & 3) * 8;
    const int row1 = (tid + 256) >> 2, c1 = ((tid + 256) & 3) * 8;

    const __nv_bfloat16* gA_hi = g_Xhi + (size_t)(m0) * KP2;
    const __nv_bfloat16* gA_lo = g_Xlo + (size_t)(m0) * KP2;
    const __nv_bfloat16* gB_hi = g_WhiT + (size_t)(n0) * KP2;
    const __nv_bfloat16* gB_lo = g_WloT + (size_t)(n0) * KP2;

    float4 rAh0, rAh1, rAl0, rAl1, rBh0, rBh1, rBl0, rBl1;
    {
        rAh0 = *(const float4*)(gA_hi + (size_t)row0 * KP2 + c0);
        rAh1 = *(const float4*)(gA_hi + (size_t)row1 * KP2 + c1);
        rAl0 = *(const float4*)(gA_lo + (size_t)row0 * KP2 + c0);
        rAl1 = *(const float4*)(gA_lo + (size_t)row1 * KP2 + c1);
        rBh0 = *(const float4*)(gB_hi + (size_t)row0 * KP2 + c0);
        rBh1 = *(const float4*)(gB_hi + (size_t)row1 * KP2 + c1);
        rBl0 = *(const float4*)(gB_lo + (size_t)row0 * KP2 + c0);
        rBl1 = *(const float4*)(gB_lo + (size_t)row1 * KP2 + c1);
        __nv_bfloat16* s = sm;
        *(float4*)(s + 0 * TILE_E + row0 * SROW + c0) = rAh0;
        *(float4*)(s + 0 * TILE_E + row1 * SROW + c1) = rAh1;
        *(float4*)(s + 1 * TILE_E + row0 * SROW + c0) = rAl0;
        *(float4*)(s + 1 * TILE_E + row1 * SROW + c1) = rAl1;
        *(float4*)(s + 2 * TILE_E + row0 * SROW + c0) = rBh0;
        *(float4*)(s + 2 * TILE_E + row1 * SROW + c1) = rBh1;
        *(float4*)(s + 3 * TILE_E + row0 * SROW + c0) = rBl0;
        *(float4*)(s + 3 * TILE_E + row1 * SROW + c1) = rBl1;
    }
    __syncthreads();

    int g = lane >> 3, rIn = lane & 7;
    int aRowOff = wr * 64 + rIn + (g & 1) * 8;
    int aColOff = (g >> 1) * 8;
    int bRowOff = wc * 32 + rIn + (g >> 1) * 8;
    int bColOff = (g & 1) * 8;

    const int NSTAGE = KP2 / KT;   // 18
    #pragma unroll 1
    for (int kt = 0; kt < NSTAGE; kt++) {
        int p = kt & 1;
        if (kt + 1 < NSTAGE) {
            int k0 = (kt + 1) * KT;
            rAh0 = *(const float4*)(gA_hi + (size_t)row0 * KP2 + k0 + c0);
            rAh1 = *(const float4*)(gA_hi + (size_t)row1 * KP2 + k0 + c1);
            rAl0 = *(const float4*)(gA_lo + (size_t)row0 * KP2 + k0 + c0);
            rAl1 = *(const float4*)(gA_lo + (size_t)row1 * KP2 + k0 + c1);
            rBh0 = *(const float4*)(gB_hi + (size_t)row0 * KP2 + k0 + c0);
            rBh1 = *(const float4*)(gB_hi + (size_t)row1 * KP2 + k0 + c1);
            rBl0 = *(const float4*)(gB_lo + (size_t)row0 * KP2 + k0 + c0);
            rBl1 = *(const float4*)(gB_lo + (size_t)row1 * KP2 + k0 + c1);
        }
        uint32_t stage = sb + (uint32_t)(p * ST_E) * 2;
        #pragma unroll
        for (int ks = 0; ks < KT / 16; ks++) {
            int k16 = ks * 16;
            uint32_t ahi[4][4], alo[4][4], bhi[2][4], blo[2][4];
            #pragma unroll
            for (int mt = 0; mt < 4; mt++) {
                uint32_t ad = stage + 2 * (0 * TILE_E + (aRowOff + mt * 16) * SROW + k16 + aColOff);
                ldsm4(ad, ahi[mt]);
                uint32_t ad2 = stage + 2 * (1 * TILE_E + (aRowOff + mt * 16) * SROW + k16 + aColOff);
                ldsm4(ad2, alo[mt]);
            }
            #pragma unroll
            for (int np = 0; np < 2; np++) {
                uint32_t bd = stage + 2 * (2 * TILE_E + (bRowOff + np * 16) * SROW + k16 + bColOff);
                ldsm4(bd, bhi[np]);
                uint32_t bd2 = stage + 2 * (3 * TILE_E + (bRowOff + np * 16) * SROW + k16 + bColOff);
                ldsm4(bd2, blo[np]);
            }
            #pragma unroll
            for (int mt = 0; mt < 4; mt++) {
                #pragma unroll
                for (int np = 0; np < 2; np++) {
                    #pragma unroll
                    for (int h = 0; h < 2; h++) {
                        int nt = np * 2 + h;
                        mma16816(acc[mt][nt], ahi[mt], bhi[np][2 * h], bhi[np][2 * h + 1]);
                        mma16816(acc[mt][nt], ahi[mt], blo[np][2 * h], blo[np][2 * h + 1]);
                        mma16816(acc[mt][nt], alo[mt], bhi[np][2 * h], bhi[np][2 * h + 1]);
                    }
                }
            }
        }
        __syncthreads();
        if (kt + 1 < NSTAGE) {
            __nv_bfloat16* s = sm + (1 - p) * ST_E;
            *(float4*)(s + 0 * TILE_E + row0 * SROW + c0) = rAh0;
            *(float4*)(s + 0 * TILE_E + row1 * SROW + c1) = rAh1;
            *(float4*)(s + 1 * TILE_E + row0 * SROW + c0) = rAl0;
            *(float4*)(s + 1 * TILE_E + row1 * SROW + c1) = rAl1;
            *(float4*)(s + 2 * TILE_E + row0 * SROW + c0) = rBh0;
            *(float4*)(s + 2 * TILE_E + row1 * SROW + c1) = rBh1;
            *(float4*)(s + 3 * TILE_E + row0 * SROW + c0) = rBl0;
            *(float4*)(s + 3 * TILE_E + row1 * SROW + c1) = rBl1;
            __syncthreads();
        }
    }

    int lrow = lane >> 2, lcol2 = (lane & 3) * 2;
    #pragma unroll
    for (int mt = 0; mt < 4; mt++) {
        #pragma unroll
        for (int nt = 0; nt < 4; nt++) {
            int col = n0 + wc * 32 + nt * 8 + lcol2;
            float2 bv = *(const float2*)(bias + col);
            int r0 = m0 + wr * 64 + mt * 16 + lrow;
            float2 v0 = make_float2(acc[mt][nt][0] + bv.x, acc[mt][nt][1] + bv.y);
            float2 v1 = make_float2(acc[mt][nt][2] + bv.x, acc[mt][nt][3] + bv.y);
            *(float2*)(out + (size_t)r0 * Dd + col) = v0;
            *(float2*)(out + (size_t)(r0 + 8) * Dd + col) = v1;
        }
    }
}

extern "C" void kernel_launch(void* const* d_in, const int* in_sizes, int n_in,
                              void* d_out, int out_size) {
    const float* frame  = (const float*)d_in[0];
    const void*  bounds = d_in[1];
    const float* Wm     = (const float*)d_in[2];
    const float* bias   = (const float*)d_in[3];
    float* out = (float*)d_out;

    cudaFuncSetAttribute(kGemmMMA, cudaFuncAttributeMaxDynamicSharedMemorySize, SM_BYTES);

    kPrep<<<24 + KP2, 512>>>(bounds, Wm);
    kChunk<<<dim3(NC, Bb), 128>>>(frame);
    kScan<<<dim3(128, Bb), 128>>>();
    kGather<<<dim3(Mm, Bb), 128>>>(frame);
    kGemmMMA<<<dim3(Dd / 128, (Bb * Mm) / 128), 256, SM_BYTES>>>(bias, out);
}

// round 11
// speedup vs baseline: 3.1077x; 1.0967x over previous
#include <cuda_runtime.h>
#include <cuda_bf16.h>
#include <math.h>
#include <stdint.h>

#define Bb 8
#define Tt 8192
#define Dd 512
#define Mm 512
#define PD 32
#define KK (Dd + PD)      // 544 (full input width; GEMM K is Dd=512 after FF split-out)
#define LC 16
#define NC (Tt / LC)      // 512

// ---- scratch (device globals; no allocation allowed) ----
__device__ float g_chunkSum[Bb * NC * Dd];            // 8 MB
__device__ float g_chunkPre[Bb * NC * Dd];            // 8 MB
__device__ float g_fine[Bb * NC * 3 * Dd];            // 24 MB: cumulative 4/8/12-row partials
__device__ float g_ffb[Mm * Dd];                      // ff @ W2 + bias (fp32, batch-independent)
__device__ int   g_s[Bb * Mm];
__device__ int   g_e[Bb * Mm];
__device__ __nv_bfloat16 g_Xhi[Bb * Mm * Dd];
__device__ __nv_bfloat16 g_Xlo[Bb * Mm * Dd];
__device__ __nv_bfloat16 g_WhiT[Dd * Dd];   // W1^T [n][k], bf16 hi  (k < 512)
__device__ __nv_bfloat16 g_WloT[Dd * Dd];

// ================ kFused: 1D grid of 128-thread blocks ================
// [0, 4096)        : chunk sums + fine partials           (c = bid&511, b = bid>>9)
// [4096, 4128)     : bounds clamp (int32/int64 autodetect)
// [4128, 6176)     : ffb = fourier @ W2 + bias  (fp32)    (2048 blocks: m = q>>2, quarter n)
// [6176, 8224)     : W1 split+transpose -> bf16 hi/lo     (2048 blocks: k = q>>2, quarter n)
#define NBLK_CHUNK (NC * Bb)                 // 4096
#define NBLK_BND   32
#define NBLK_FFB   (Mm * 4)                  // 2048
#define NBLK_W     (Dd * 4)                  // 2048
#define NBLK_TOTAL (NBLK_CHUNK + NBLK_BND + NBLK_FFB + NBLK_W)

__global__ void __launch_bounds__(128) kFused(const float* __restrict__ frame,
                                              const void* __restrict__ bounds,
                                              const float* __restrict__ W,
                                              const float* __restrict__ bias) {
    int bid = blockIdx.x, tid = threadIdx.x;

    if (bid < NBLK_CHUNK) {
        // ---- chunk sums + fine partials ----
        int c = bid & (NC - 1), b = bid >> 9, t4 = tid;
        const float4* f = (const float4*)frame;
        float4* fine = (float4*)g_fine;
        float4 acc = make_float4(0.f, 0.f, 0.f, 0.f);
        int base = (b * Tt + c * LC) * (Dd / 4) + t4;
        size_t fbase = ((size_t)(b * NC + c) * 3) * (Dd / 4) + t4;
        #pragma unroll
        for (int r = 0; r < LC; r++) {
            float4 v = f[base + r * (Dd / 4)];
            acc.x += v.x; acc.y += v.y; acc.z += v.z; acc.w += v.w;
            if (r == 3)  fine[fbase + 0 * (Dd / 4)] = acc;
            if (r == 7)  fine[fbase + 1 * (Dd / 4)] = acc;
            if (r == 11) fine[fbase + 2 * (Dd / 4)] = acc;
        }
        ((float4*)g_chunkSum)[(b * NC + c) * (Dd / 4) + t4] = acc;
        return;
    }
    bid -= NBLK_CHUNK;

    if (bid < NBLK_BND) {
        // ---- clamp bounds; int32/int64 autodetect on first 128 words ----
        __shared__ int flag;
        if (tid == 0) flag = 0;
        __syncthreads();
        {
            const int* w = (const int*)bounds;
            if (w[2 * tid + 1] != 0) flag = 1;   // benign race
        }
        __syncthreads();
        bool isI64 = (flag == 0);
        int idx = bid * 128 + tid;               // 0..4095
        int b = idx >> 9, m = idx & 511;
        long long sv, ev;
        if (isI64) {
            const long long* p = (const long long*)bounds;
            sv = p[((long long)b * Mm + m) * 2];
            ev = p[((long long)b * Mm + m) * 2 + 1];
        } else {
            const int* p = (const int*)bounds;
            sv = p[(b * Mm + m) * 2];
            ev = p[(b * Mm + m) * 2 + 1];
        }
        long long s = sv; if (s < 0) s = 0; if (s > Tt - 1) s = Tt - 1;
        long long e = ev; if (e > Tt) e = Tt; if (e < s + 1) e = s + 1;
        g_s[b * Mm + m] = (int)s;
        g_e[b * Mm + m] = (int)e;
        return;
    }
    bid -= NBLK_BND;

    if (bid < NBLK_FFB) {
        // ---- ffb[m][n] = sum_j ff[m][j] * W[512+j][n] + bias[n]  (fp32) ----
        int m = bid >> 2, q = bid & 3;
        int n = q * 128 + tid;
        __shared__ float ffs[PD];
        if (tid < PD / 2) {
            double pos = (double)m / (double)(Mm - 1);
            double f = exp(log(1000.0) * (double)tid / (double)(PD / 2 - 1));
            double a = pos * f;
            ffs[tid] = (float)sin(a);
            ffs[PD / 2 + tid] = (float)cos(a);
        }
        __syncthreads();
        float acc = bias[n];
        #pragma unroll
        for (int j = 0; j < PD; j++)
            acc = fmaf(ffs[j], W[(Dd + j) * Dd + n], acc);
        g_ffb[m * Dd + n] = acc;
        return;
    }
    bid -= NBLK_FFB;

    {
        // ---- split + transpose W1 -> [n][k] bf16 hi/lo (k < 512) ----
        int k = bid >> 2, q = bid & 3;
        int n = q * 128 + tid;
        float v = W[k * Dd + n];
        __nv_bfloat16 h = __float2bfloat16(v);
        float rlo = v - __bfloat162float(h);
        g_WhiT[n * Dd + k] = h;
        g_WloT[n * Dd + k] = __float2bfloat16(rlo);
    }
}

// ---------------- kScan: exclusive prefix over NC chunks (4 warps/block) ----------------
__global__ void __launch_bounds__(128) kScan() {
    int d4 = blockIdx.x, b = blockIdx.y;
    int tid = threadIdx.x, wid = tid >> 5, lane = tid & 31;
    __shared__ float4 wtot[4];

    const float4* cs = (const float4*)g_chunkSum;
    float4* cp = (float4*)g_chunkPre;
    const int CPL = 4;
    int cbase = (wid * 32 + lane) * CPL;

    float4 v[CPL];
    float4 s = make_float4(0.f, 0.f, 0.f, 0.f);
    #pragma unroll
    for (int j = 0; j < CPL; j++) {
        v[j] = cs[(b * NC + cbase + j) * (Dd / 4) + d4];
        s.x += v[j].x; s.y += v[j].y; s.z += v[j].z; s.w += v[j].w;
    }
    float4 incl = s;
    #pragma unroll
    for (int off = 1; off < 32; off <<= 1) {
        float nx = __shfl_up_sync(0xffffffffu, incl.x, off);
        float ny = __shfl_up_sync(0xffffffffu, incl.y, off);
        float nz = __shfl_up_sync(0xffffffffu, incl.z, off);
        float nw = __shfl_up_sync(0xffffffffu, incl.w, off);
        if (lane >= off) { incl.x += nx; incl.y += ny; incl.z += nz; incl.w += nw; }
    }
    if (lane == 31) wtot[wid] = incl;
    __syncthreads();
    float4 wpre = make_float4(0.f, 0.f, 0.f, 0.f);
    #pragma unroll
    for (int w = 0; w < 4; w++) {
        if (w < wid) {
            float4 t = wtot[w];
            wpre.x += t.x; wpre.y += t.y; wpre.z += t.z; wpre.w += t.w;
        }
    }
    float4 run = make_float4(wpre.x + incl.x - s.x, wpre.y + incl.y - s.y,
                             wpre.z + incl.z - s.z, wpre.w + incl.w - s.w);
    #pragma unroll
    for (int j = 0; j < CPL; j++) {
        cp[(b * NC + cbase + j) * (Dd / 4) + d4] = run;
        run.x += v[j].x; run.y += v[j].y; run.z += v[j].z; run.w += v[j].w;
    }
}

// ---------------- kGather: segment means -> bf16 hi/lo (2-level prefix) ----------------
__global__ void __launch_bounds__(128) kGather(const float* __restrict__ frame) {
    int m = blockIdx.x, b = blockIdx.y, t4 = threadIdx.x;
    int idx = b * Mm + m;
    int s = g_s[idx], e = g_e[idx];
    int csk = s >> 4;
    int cek = e >> 4; if (cek > NC - 1) cek = NC - 1;

    const float4* f  = (const float4*)frame;
    const float4* cp = (const float4*)g_chunkPre;
    const float4* fine = (const float4*)g_fine;

    float4 accs = cp[(b * NC + csk) * (Dd / 4) + t4];
    int fs = (s - csk * LC) >> 2;
    if (fs > 0) {
        float4 fv = fine[((size_t)(b * NC + csk) * 3 + (fs - 1)) * (Dd / 4) + t4];
        accs.x += fv.x; accs.y += fv.y; accs.z += fv.z; accs.w += fv.w;
    }
    for (int t = csk * LC + 4 * fs; t < s; t++) {
        float4 v = f[(b * Tt + t) * (Dd / 4) + t4];
        accs.x += v.x; accs.y += v.y; accs.z += v.z; accs.w += v.w;
    }
    float4 acce = cp[(b * NC + cek) * (Dd / 4) + t4];
    int de = e - cek * LC;
    int fe = de >> 2; if (fe > 3) fe = 3;
    if (fe > 0) {
        float4 fv = fine[((size_t)(b * NC + cek) * 3 + (fe - 1)) * (Dd / 4) + t4];
        acce.x += fv.x; acce.y += fv.y; acce.z += fv.z; acce.w += fv.w;
    }
    for (int t = cek * LC + 4 * fe; t < e; t++) {
        float4 v = f[(b * Tt + t) * (Dd / 4) + t4];
        acce.x += v.x; acce.y += v.y; acce.z += v.z; acce.w += v.w;
    }

    float inv = 1.f / (float)(e - s);
    float4 r = make_float4((acce.x - accs.x) * inv, (acce.y - accs.y) * inv,
                           (acce.z - accs.z) * inv, (acce.w - accs.w) * inv);
    __nv_bfloat16 h0 = __float2bfloat16(r.x), h1 = __float2bfloat16(r.y);
    __nv_bfloat16 h2 = __float2bfloat16(r.z), h3 = __float2bfloat16(r.w);
    uint2 hh, ll;
    hh.x = (uint32_t)__bfloat16_as_ushort(h0) | ((uint32_t)__bfloat16_as_ushort(h1) << 16);
    hh.y = (uint32_t)__bfloat16_as_ushort(h2) | ((uint32_t)__bfloat16_as_ushort(h3) << 16);
    __nv_bfloat16 l0 = __float2bfloat16(r.x - __bfloat162float(h0));
    __nv_bfloat16 l1 = __float2bfloat16(r.y - __bfloat162float(h1));
    __nv_bfloat16 l2 = __float2bfloat16(r.z - __bfloat162float(h2));
    __nv_bfloat16 l3 = __float2bfloat16(r.w - __bfloat162float(h3));
    ll.x = (uint32_t)__bfloat16_as_ushort(l0) | ((uint32_t)__bfloat16_as_ushort(l1) << 16);
    ll.y = (uint32_t)__bfloat16_as_ushort(l2) | ((uint32_t)__bfloat16_as_ushort(l3) << 16);

    *(uint2*)(g_Xhi + (size_t)idx * Dd + 4 * t4) = hh;
    *(uint2*)(g_Xlo + (size_t)idx * Dd + 4 * t4) = ll;
}

// ================= mma.sync bf16 GEMM, K = 512 =================
// out[4096,512] = X @ W1 + ffb  via 3-term bf16 split.
// CTA tile 128(m) x 128(n), KT=32. 8 warps = 2(m) x 4(n); warp tile 64x32.

#define KT 32
#define SROW 40
#define TILE_E (128 * SROW)
#define ST_E   (4 * TILE_E)
#define SM_BYTES (2 * ST_E * 2)          // 81920

static __device__ __forceinline__ uint32_t smem_u32(const void* p) {
    uint32_t a;
    asm("{ .reg .u64 t; cvta.to.shared.u64 t, %1; cvt.u32.u64 %0, t; }" : "=r"(a) : "l"(p));
    return a;
}
static __device__ __forceinline__ void ldsm4(uint32_t addr, uint32_t* r) {
    asm volatile("ldmatrix.sync.aligned.m8n8.x4.shared.b16 {%0,%1,%2,%3}, [%4];"
                 : "=r"(r[0]), "=r"(r[1]), "=r"(r[2]), "=r"(r[3]) : "r"(addr));
}
static __device__ __forceinline__ void mma16816(float* c, const uint32_t* a, uint32_t b0, uint32_t b1) {
    asm volatile(
        "mma.sync.aligned.m16n8k16.row.col.f32.bf16.bf16.f32 "
        "{%0,%1,%2,%3},{%4,%5,%6,%7},{%8,%9},{%0,%1,%2,%3};"
        : "+f"(c[0]), "+f"(c[1]), "+f"(c[2]), "+f"(c[3])
        : "r"(a[0]), "r"(a[1]), "r"(a[2]), "r"(a[3]), "r"(b0), "r"(b1));
}

__global__ void __launch_bounds__(256, 1)
kGemmMMA(float* __restrict__ out) {
    extern __shared__ __align__(16) __nv_bfloat16 sm[];
    uint32_t sb = smem_u32(sm);
    int tid = threadIdx.x;
    int wid = tid >> 5, lane = tid & 31;
    int n0 = blockIdx.x * 128, m0 = blockIdx.y * 128;
    int wr = wid >> 2, wc = wid & 3;

    float acc[4][4][4];
    #pragma unroll
    for (int i = 0; i < 4; i++)
        #pragma unroll
        for (int j = 0; j < 4; j++)
            #pragma unroll
            for (int q = 0; q < 4; q++) acc[i][j][q] = 0.f;

    const int row0 = tid >> 2, c0 = (tid & 3) * 8;
    const int row1 = (tid + 256) >> 2, c1 = ((tid + 256) & 3) * 8;

    const __nv_bfloat16* gA_hi = g_Xhi + (size_t)(m0) * Dd;
    const __nv_bfloat16* gA_lo = g_Xlo + (size_t)(m0) * Dd;
    const __nv_bfloat16* gB_hi = g_WhiT + (size_t)(n0) * Dd;
    const __nv_bfloat16* gB_lo = g_WloT + (size_t)(n0) * Dd;

    float4 rAh0, rAh1, rAl0, rAl1, rBh0, rBh1, rBl0, rBl1;
    {
        rAh0 = *(const float4*)(gA_hi + (size_t)row0 * Dd + c0);
        rAh1 = *(const float4*)(gA_hi + (size_t)row1 * Dd + c1);
        rAl0 = *(const float4*)(gA_lo + (size_t)row0 * Dd + c0);
        rAl1 = *(const float4*)(gA_lo + (size_t)row1 * Dd + c1);
        rBh0 = *(const float4*)(gB_hi + (size_t)row0 * Dd + c0);
        rBh1 = *(const float4*)(gB_hi + (size_t)row1 * Dd + c1);
        rBl0 = *(const float4*)(gB_lo + (size_t)row0 * Dd + c0);
        rBl1 = *(const float4*)(gB_lo + (size_t)row1 * Dd + c1);
        __nv_bfloat16* s = sm;
        *(float4*)(s + 0 * TILE_E + row0 * SROW + c0) = rAh0;
        *(float4*)(s + 0 * TILE_E + row1 * SROW + c1) = rAh1;
        *(float4*)(s + 1 * TILE_E + row0 * SROW + c0) = rAl0;
        *(float4*)(s + 1 * TILE_E + row1 * SROW + c1) = rAl1;
        *(float4*)(s + 2 * TILE_E + row0 * SROW + c0) = rBh0;
        *(float4*)(s + 2 * TILE_E + row1 * SROW + c1) = rBh1;
        *(float4*)(s + 3 * TILE_E + row0 * SROW + c0) = rBl0;
        *(float4*)(s + 3 * TILE_E + row1 * SROW + c1) = rBl1;
    }
    __syncthreads();

    int g = lane >> 3, rIn = lane & 7;
    int aRowOff = wr * 64 + rIn + (g & 1) * 8;
    int aColOff = (g >> 1) * 8;
    int bRowOff = wc * 32 + rIn + (g >> 1) * 8;
    int bColOff = (g & 1) * 8;

    const int NSTAGE = Dd / KT;   // 16
    #pragma unroll 1
    for (int kt = 0; kt < NSTAGE; kt++) {
        int p = kt & 1;
        if (kt + 1 < NSTAGE) {
            int k0 = (kt + 1) * KT;
            rAh0 = *(const float4*)(gA_hi + (size_t)row0 * Dd + k0 + c0);
            rAh1 = *(const float4*)(gA_hi + (size_t)row1 * Dd + k0 + c1);
            rAl0 = *(const float4*)(gA_lo + (size_t)row0 * Dd + k0 + c0);
            rAl1 = *(const float4*)(gA_lo + (size_t)row1 * Dd + k0 + c1);
            rBh0 = *(const float4*)(gB_hi + (size_t)row0 * Dd + k0 + c0);
            rBh1 = *(const float4*)(gB_hi + (size_t)row1 * Dd + k0 + c1);
            rBl0 = *(const float4*)(gB_lo + (size_t)row0 * Dd + k0 + c0);
            rBl1 = *(const float4*)(gB_lo + (size_t)row1 * Dd + k0 + c1);
        }
        uint32_t stage = sb + (uint32_t)(p * ST_E) * 2;
        #pragma unroll
        for (int ks = 0; ks < KT / 16; ks++) {
            int k16 = ks * 16;
            uint32_t ahi[4][4], alo[4][4], bhi[2][4], blo[2][4];
            #pragma unroll
            for (int mt = 0; mt < 4; mt++) {
                uint32_t ad = stage + 2 * (0 * TILE_E + (aRowOff + mt * 16) * SROW + k16 + aColOff);
                ldsm4(ad, ahi[mt]);
                uint32_t ad2 = stage + 2 * (1 * TILE_E + (aRowOff + mt * 16) * SROW + k16 + aColOff);
                ldsm4(ad2, alo[mt]);
            }
            #pragma unroll
            for (int np = 0; np < 2; np++) {
                uint32_t bd = stage + 2 * (2 * TILE_E + (bRowOff + np * 16) * SROW + k16 + bColOff);
                ldsm4(bd, bhi[np]);
                uint32_t bd2 = stage + 2 * (3 * TILE_E + (bRowOff + np * 16) * SROW + k16 + bColOff);
                ldsm4(bd2, blo[np]);
            }
            #pragma unroll
            for (int mt = 0; mt < 4; mt++) {
                #pragma unroll
                for (int np = 0; np < 2; np++) {
                    #pragma unroll
                    for (int h = 0; h < 2; h++) {
                        int nt = np * 2 + h;
                        mma16816(acc[mt][nt], ahi[mt], bhi[np][2 * h], bhi[np][2 * h + 1]);
                        mma16816(acc[mt][nt], ahi[mt], blo[np][2 * h], blo[np][2 * h + 1]);
                        mma16816(acc[mt][nt], alo[mt], bhi[np][2 * h], bhi[np][2 * h + 1]);
                    }
                }
            }
        }
        __syncthreads();
        if (kt + 1 < NSTAGE) {
            __nv_bfloat16* s = sm + (1 - p) * ST_E;
            *(float4*)(s + 0 * TILE_E + row0 * SROW + c0) = rAh0;
            *(float4*)(s + 0 * TILE_E + row1 * SROW + c1) = rAh1;
            *(float4*)(s + 1 * TILE_E + row0 * SROW + c0) = rAl0;
            *(float4*)(s + 1 * TILE_E + row1 * SROW + c1) = rAl1;
            *(float4*)(s + 2 * TILE_E + row0 * SROW + c0) = rBh0;
            *(float4*)(s + 2 * TILE_E + row1 * SROW + c1) = rBh1;
            *(float4*)(s + 3 * TILE_E + row0 * SROW + c0) = rBl0;
            *(float4*)(s + 3 * TILE_E + row1 * SROW + c1) = rBl1;
            __syncthreads();
        }
    }

    // epilogue: per-row bias from ffb (m index modulo Mm — rows are (b*Mm + m))
    int lrow = lane >> 2, lcol2 = (lane & 3) * 2;
    #pragma unroll
    for (int mt = 0; mt < 4; mt++) {
        #pragma unroll
        for (int nt = 0; nt < 4; nt++) {
            int col = n0 + wc * 32 + nt * 8 + lcol2;
            int r0 = m0 + wr * 64 + mt * 16 + lrow;
            int mm0 = r0 & (Mm - 1);            // row index within batch (Mm = 512)
            float2 fb0 = *(const float2*)(g_ffb + mm0 * Dd + col);
            float2 fb1 = *(const float2*)(g_ffb + ((r0 + 8) & (Mm - 1)) * Dd + col);
            float2 v0 = make_float2(acc[mt][nt][0] + fb0.x, acc[mt][nt][1] + fb0.y);
            float2 v1 = make_float2(acc[mt][nt][2] + fb1.x, acc[mt][nt][3] + fb1.y);
            *(float2*)(out + (size_t)r0 * Dd + col) = v0;
            *(float2*)(out + (size_t)(r0 + 8) * Dd + col) = v1;
        }
    }
}

extern "C" void kernel_launch(void* const* d_in, const int* in_sizes, int n_in,
                              void* d_out, int out_size) {
    const float* frame  = (const float*)d_in[0];
    const void*  bounds = d_in[1];
    const float* Wm     = (const float*)d_in[2];
    const float* bias   = (const float*)d_in[3];
    float* out = (float*)d_out;

    cudaFuncSetAttribute(kGemmMMA, cudaFuncAttributeMaxDynamicSharedMemorySize, SM_BYTES);

    kFused<<<NBLK_TOTAL, 128>>>(frame, bounds, Wm, bias);
    kScan<<<dim3(128, Bb), 128>>>();
    kGather<<<dim3(Mm, Bb), 128>>>(frame);
    kGemmMMA<<<dim3(Dd / 128, (Bb * Mm) / 128), 256, SM_BYTES>>>(out);
}

// round 12
// speedup vs baseline: 3.2120x; 1.0336x over previous
#include <cuda_runtime.h>
#include <cuda_fp16.h>
#include <math.h>
#include <stdint.h>

#define Bb 8
#define Tt 8192
#define Dd 512
#define Mm 512
#define PD 32
#define LC 16
#define NC (Tt / LC)      // 512

// ---- scratch (device globals; no allocation allowed) ----
__device__ float g_chunkSum[Bb * NC * Dd];            // 8 MB
__device__ float g_chunkPre[Bb * NC * Dd];            // 8 MB
__device__ float g_fine[Bb * NC * 3 * Dd];            // 24 MB: cumulative 4/8/12-row partials
__device__ float g_ffb[Mm * Dd];                      // ff @ W2 + bias (fp32, batch-independent)
__device__ int   g_s[Bb * Mm];
__device__ int   g_e[Bb * Mm];
__device__ __half g_Xh[Bb * Mm * Dd];                 // fp16(X)
__device__ __half g_WhT[Dd * Dd];                     // W1^T [n][k], fp16 hi
__device__ __half g_WlT[Dd * Dd];                     // W1^T [n][k], fp16 lo (W - Wh, exact to ~2^-22)

// ================ kFused: 1D grid of 128-thread blocks ================
#define NBLK_CHUNK (NC * Bb)                 // 4096
#define NBLK_BND   32
#define NBLK_FFB   (Mm * 4)                  // 2048
#define NBLK_W     (Dd * 4)                  // 2048
#define NBLK_TOTAL (NBLK_CHUNK + NBLK_BND + NBLK_FFB + NBLK_W)

__global__ void __launch_bounds__(128) kFused(const float* __restrict__ frame,
                                              const void* __restrict__ bounds,
                                              const float* __restrict__ W,
                                              const float* __restrict__ bias) {
    int bid = blockIdx.x, tid = threadIdx.x;

    if (bid < NBLK_CHUNK) {
        // ---- chunk sums + fine partials ----
        int c = bid & (NC - 1), b = bid >> 9, t4 = tid;
        const float4* f = (const float4*)frame;
        float4* fine = (float4*)g_fine;
        float4 acc = make_float4(0.f, 0.f, 0.f, 0.f);
        int base = (b * Tt + c * LC) * (Dd / 4) + t4;
        size_t fbase = ((size_t)(b * NC + c) * 3) * (Dd / 4) + t4;
        #pragma unroll
        for (int r = 0; r < LC; r++) {
            float4 v = f[base + r * (Dd / 4)];
            acc.x += v.x; acc.y += v.y; acc.z += v.z; acc.w += v.w;
            if (r == 3)  fine[fbase + 0 * (Dd / 4)] = acc;
            if (r == 7)  fine[fbase + 1 * (Dd / 4)] = acc;
            if (r == 11) fine[fbase + 2 * (Dd / 4)] = acc;
        }
        ((float4*)g_chunkSum)[(b * NC + c) * (Dd / 4) + t4] = acc;
        return;
    }
    bid -= NBLK_CHUNK;

    if (bid < NBLK_BND) {
        // ---- clamp bounds; int32/int64 autodetect ----
        __shared__ int flag;
        if (tid == 0) flag = 0;
        __syncthreads();
        {
            const int* w = (const int*)bounds;
            if (w[2 * tid + 1] != 0) flag = 1;   // benign race
        }
        __syncthreads();
        bool isI64 = (flag == 0);
        int idx = bid * 128 + tid;               // 0..4095
        int b = idx >> 9, m = idx & 511;
        long long sv, ev;
        if (isI64) {
            const long long* p = (const long long*)bounds;
            sv = p[((long long)b * Mm + m) * 2];
            ev = p[((long long)b * Mm + m) * 2 + 1];
        } else {
            const int* p = (const int*)bounds;
            sv = p[(b * Mm + m) * 2];
            ev = p[(b * Mm + m) * 2 + 1];
        }
        long long s = sv; if (s < 0) s = 0; if (s > Tt - 1) s = Tt - 1;
        long long e = ev; if (e > Tt) e = Tt; if (e < s + 1) e = s + 1;
        g_s[b * Mm + m] = (int)s;
        g_e[b * Mm + m] = (int)e;
        return;
    }
    bid -= NBLK_BND;

    if (bid < NBLK_FFB) {
        // ---- ffb[m][n] = sum_j ff[m][j] * W[512+j][n] + bias[n]  (fp32) ----
        int m = bid >> 2, q = bid & 3;
        int n = q * 128 + tid;
        __shared__ float ffs[PD];
        if (tid < PD / 2) {
            double pos = (double)m / (double)(Mm - 1);
            double f = exp(log(1000.0) * (double)tid / (double)(PD / 2 - 1));
            double a = pos * f;
            ffs[tid] = (float)sin(a);
            ffs[PD / 2 + tid] = (float)cos(a);
        }
        __syncthreads();
        float acc = bias[n];
        #pragma unroll
        for (int j = 0; j < PD; j++)
            acc = fmaf(ffs[j], W[(Dd + j) * Dd + n], acc);
        g_ffb[m * Dd + n] = acc;
        return;
    }
    bid -= NBLK_FFB;

    {
        // ---- split + transpose W1 -> [n][k] fp16 hi/lo (k < 512) ----
        int k = bid >> 2, q = bid & 3;
        int n = q * 128 + tid;
        float v = W[k * Dd + n];
        __half h = __float2half_rn(v);
        g_WhT[n * Dd + k] = h;
        g_WlT[n * Dd + k] = __float2half_rn(v - __half2float(h));
    }
}

// ---------------- kScan: exclusive prefix over NC chunks (4 warps/block) ----------------
__global__ void __launch_bounds__(128) kScan() {
    int d4 = blockIdx.x, b = blockIdx.y;
    int tid = threadIdx.x, wid = tid >> 5, lane = tid & 31;
    __shared__ float4 wtot[4];

    const float4* cs = (const float4*)g_chunkSum;
    float4* cp = (float4*)g_chunkPre;
    const int CPL = 4;
    int cbase = (wid * 32 + lane) * CPL;

    float4 v[CPL];
    float4 s = make_float4(0.f, 0.f, 0.f, 0.f);
    #pragma unroll
    for (int j = 0; j < CPL; j++) {
        v[j] = cs[(b * NC + cbase + j) * (Dd / 4) + d4];
        s.x += v[j].x; s.y += v[j].y; s.z += v[j].z; s.w += v[j].w;
    }
    float4 incl = s;
    #pragma unroll
    for (int off = 1; off < 32; off <<= 1) {
        float nx = __shfl_up_sync(0xffffffffu, incl.x, off);
        float ny = __shfl_up_sync(0xffffffffu, incl.y, off);
        float nz = __shfl_up_sync(0xffffffffu, incl.z, off);
        float nw = __shfl_up_sync(0xffffffffu, incl.w, off);
        if (lane >= off) { incl.x += nx; incl.y += ny; incl.z += nz; incl.w += nw; }
    }
    if (lane == 31) wtot[wid] = incl;
    __syncthreads();
    float4 wpre = make_float4(0.f, 0.f, 0.f, 0.f);
    #pragma unroll
    for (int w = 0; w < 4; w++) {
        if (w < wid) {
            float4 t = wtot[w];
            wpre.x += t.x; wpre.y += t.y; wpre.z += t.z; wpre.w += t.w;
        }
    }
    float4 run = make_float4(wpre.x + incl.x - s.x, wpre.y + incl.y - s.y,
                             wpre.z + incl.z - s.z, wpre.w + incl.w - s.w);
    #pragma unroll
    for (int j = 0; j < CPL; j++) {
        cp[(b * NC + cbase + j) * (Dd / 4) + d4] = run;
        run.x += v[j].x; run.y += v[j].y; run.z += v[j].z; run.w += v[j].w;
    }
}

// ---------------- kGather: segment means -> fp16 (2-level prefix) ----------------
__global__ void __launch_bounds__(128) kGather(const float* __restrict__ frame) {
    int m = blockIdx.x, b = blockIdx.y, t4 = threadIdx.x;
    int idx = b * Mm + m;
    int s = g_s[idx], e = g_e[idx];
    int csk = s >> 4;
    int cek = e >> 4; if (cek > NC - 1) cek = NC - 1;

    const float4* f  = (const float4*)frame;
    const float4* cp = (const float4*)g_chunkPre;
    const float4* fine = (const float4*)g_fine;

    float4 accs = cp[(b * NC + csk) * (Dd / 4) + t4];
    int fs = (s - csk * LC) >> 2;
    if (fs > 0) {
        float4 fv = fine[((size_t)(b * NC + csk) * 3 + (fs - 1)) * (Dd / 4) + t4];
        accs.x += fv.x; accs.y += fv.y; accs.z += fv.z; accs.w += fv.w;
    }
    for (int t = csk * LC + 4 * fs; t < s; t++) {
        float4 v = f[(b * Tt + t) * (Dd / 4) + t4];
        accs.x += v.x; accs.y += v.y; accs.z += v.z; accs.w += v.w;
    }
    float4 acce = cp[(b * NC + cek) * (Dd / 4) + t4];
    int de = e - cek * LC;
    int fe = de >> 2; if (fe > 3) fe = 3;
    if (fe > 0) {
        float4 fv = fine[((size_t)(b * NC + cek) * 3 + (fe - 1)) * (Dd / 4) + t4];
        acce.x += fv.x; acce.y += fv.y; acce.z += fv.z; acce.w += fv.w;
    }
    for (int t = cek * LC + 4 * fe; t < e; t++) {
        float4 v = f[(b * Tt + t) * (Dd / 4) + t4];
        acce.x += v.x; acce.y += v.y; acce.z += v.z; acce.w += v.w;
    }

    float inv = 1.f / (float)(e - s);
    __half2 p0 = __floats2half2_rn((acce.x - accs.x) * inv, (acce.y - accs.y) * inv);
    __half2 p1 = __floats2half2_rn((acce.z - accs.z) * inv, (acce.w - accs.w) * inv);
    uint2 hh;
    hh.x = *(uint32_t*)&p0;
    hh.y = *(uint32_t*)&p1;
    *(uint2*)(g_Xh + (size_t)idx * Dd + 4 * t4) = hh;
}

// ================= mma.sync fp16 2-term GEMM, K = 512, cp.async 4-stage =================
// out[4096,512] = Xh @ (Wh + Wl) + ffb.
// CTA tile 128(m) x 128(n), KT=32, 8 warps = 2(m) x 4(n); warp tile 64x32.

#define KT 32
#define SROW 40                              // padded row stride (fp16 elems); 80 B
#define TILE_E (128 * SROW)                  // 5120 fp16 per tile
#define TILE_B (TILE_E * 2)                  // 10240 B
#define STAGE_B (3 * TILE_B)                 // A, Bh, Bl  = 30720 B
#define NSTAGES 4
#define SM_BYTES (NSTAGES * STAGE_B)         // 122880 B

static __device__ __forceinline__ uint32_t smem_u32(const void* p) {
    uint32_t a;
    asm("{ .reg .u64 t; cvta.to.shared.u64 t, %1; cvt.u32.u64 %0, t; }" : "=r"(a) : "l"(p));
    return a;
}
static __device__ __forceinline__ void cpasync16(uint32_t saddr, const void* gptr) {
    asm volatile("cp.async.cg.shared.global [%0], [%1], 16;" :: "r"(saddr), "l"(gptr));
}
static __device__ __forceinline__ void cpcommit() {
    asm volatile("cp.async.commit_group;" ::: "memory");
}
template <int N>
static __device__ __forceinline__ void cpwait() {
    asm volatile("cp.async.wait_group %0;" :: "n"(N) : "memory");
}
static __device__ __forceinline__ void ldsm4(uint32_t addr, uint32_t* r) {
    asm volatile("ldmatrix.sync.aligned.m8n8.x4.shared.b16 {%0,%1,%2,%3}, [%4];"
                 : "=r"(r[0]), "=r"(r[1]), "=r"(r[2]), "=r"(r[3]) : "r"(addr));
}
static __device__ __forceinline__ void mma16816(float* c, const uint32_t* a, uint32_t b0, uint32_t b1) {
    asm volatile(
        "mma.sync.aligned.m16n8k16.row.col.f32.f16.f16.f32 "
        "{%0,%1,%2,%3},{%4,%5,%6,%7},{%8,%9},{%0,%1,%2,%3};"
        : "+f"(c[0]), "+f"(c[1]), "+f"(c[2]), "+f"(c[3])
        : "r"(a[0]), "r"(a[1]), "r"(a[2]), "r"(a[3]), "r"(b0), "r"(b1));
}

__global__ void __launch_bounds__(256, 1)
kGemmMMA(float* __restrict__ out) {
    extern __shared__ __align__(16) char sm[];
    uint32_t sb = smem_u32(sm);
    int tid = threadIdx.x;
    int wid = tid >> 5, lane = tid & 31;
    int n0 = blockIdx.x * 128, m0 = blockIdx.y * 128;
    int wr = wid >> 2, wc = wid & 3;

    const __half* gA = g_Xh  + (size_t)m0 * Dd;
    const __half* gBh = g_WhT + (size_t)n0 * Dd;
    const __half* gBl = g_WlT + (size_t)n0 * Dd;

    // loader mapping: 512 16B-chunks per tile; thread does chunks tid*2, tid*2+1
    const int lrow0 = tid >> 1, lcq0 = (tid & 1) * 2;   // rows 0..127, chunk-pairs

    // issue one stage's loads (A, Bh, Bl)
    auto load_stage = [&](int st, int k0) {
        uint32_t sbase = sb + st * STAGE_B;
        #pragma unroll
        for (int i = 0; i < 2; i++) {
            int row = lrow0, cq = lcq0 + i;             // cq 0..3 -> 8 fp16 each
            uint32_t soff = row * (SROW * 2) + cq * 16;
            const __half* ga = gA + (size_t)row * Dd + k0 + cq * 8;
            const __half* gh = gBh + (size_t)row * Dd + k0 + cq * 8;
            const __half* gl = gBl + (size_t)row * Dd + k0 + cq * 8;
            cpasync16(sbase + soff, ga);
            cpasync16(sbase + TILE_B + soff, gh);
            cpasync16(sbase + 2 * TILE_B + soff, gl);
        }
    };

    float acc[4][4][4];
    #pragma unroll
    for (int i = 0; i < 4; i++)
        #pragma unroll
        for (int j = 0; j < 4; j++)
            #pragma unroll
            for (int q = 0; q < 4; q++) acc[i][j][q] = 0.f;

    // prologue: stages 0..2
    #pragma unroll
    for (int s = 0; s < 3; s++) { load_stage(s, s * KT); cpcommit(); }

    int g = lane >> 3, rIn = lane & 7;
    int aRowOff = wr * 64 + rIn + (g & 1) * 8;
    int aColOff = (g >> 1) * 8;
    int bRowOff = wc * 32 + rIn + (g >> 1) * 8;
    int bColOff = (g & 1) * 8;

    const int NKT = Dd / KT;   // 16
    #pragma unroll 1
    for (int kt = 0; kt < NKT; kt++) {
        cpwait<2>();
        __syncthreads();
        // issue loads for stage kt+3 before computing (overlap)
        if (kt + 3 < NKT) load_stage((kt + 3) & 3, (kt + 3) * KT);
        cpcommit();

        uint32_t stage = sb + (kt & 3) * STAGE_B;
        #pragma unroll
        for (int ks = 0; ks < KT / 16; ks++) {
            int k16 = ks * 16;
            uint32_t a[4][4], bh[2][4], bl[2][4];
            #pragma unroll
            for (int mt = 0; mt < 4; mt++) {
                uint32_t ad = stage + 2 * ((aRowOff + mt * 16) * SROW + k16 + aColOff);
                ldsm4(ad, a[mt]);
            }
            #pragma unroll
            for (int np = 0; np < 2; np++) {
                uint32_t bd = stage + TILE_B + 2 * ((bRowOff + np * 16) * SROW + k16 + bColOff);
                ldsm4(bd, bh[np]);
                uint32_t bd2 = stage + 2 * TILE_B + 2 * ((bRowOff + np * 16) * SROW + k16 + bColOff);
                ldsm4(bd2, bl[np]);
            }
            #pragma unroll
            for (int mt = 0; mt < 4; mt++) {
                #pragma unroll
                for (int np = 0; np < 2; np++) {
                    #pragma unroll
                    for (int h = 0; h < 2; h++) {
                        int nt = np * 2 + h;
                        mma16816(acc[mt][nt], a[mt], bh[np][2 * h], bh[np][2 * h + 1]);
                        mma16816(acc[mt][nt], a[mt], bl[np][2 * h], bl[np][2 * h + 1]);
                    }
                }
            }
        }
    }

    // epilogue: per-row bias from ffb (rows are b*Mm + m; Mm == Dd == 512)
    int lrow = lane >> 2, lcol2 = (lane & 3) * 2;
    #pragma unroll
    for (int mt = 0; mt < 4; mt++) {
        #pragma unroll
        for (int nt = 0; nt < 4; nt++) {
            int col = n0 + wc * 32 + nt * 8 + lcol2;
            int r0 = m0 + wr * 64 + mt * 16 + lrow;
            int mm0 = r0 & (Mm - 1);
            float2 fb0 = *(const float2*)(g_ffb + mm0 * Dd + col);
            float2 fb1 = *(const float2*)(g_ffb + ((r0 + 8) & (Mm - 1)) * Dd + col);
            float2 v0 = make_float2(acc[mt][nt][0] + fb0.x, acc[mt][nt][1] + fb0.y);
            float2 v1 = make_float2(acc[mt][nt][2] + fb1.x, acc[mt][nt][3] + fb1.y);
            *(float2*)(out + (size_t)r0 * Dd + col) = v0;
            *(float2*)(out + (size_t)(r0 + 8) * Dd + col) = v1;
        }
    }
}

extern "C" void kernel_launch(void* const* d_in, const int* in_sizes, int n_in,
                              void* d_out, int out_size) {
    const float* frame  = (const float*)d_in[0];
    const void*  bounds = d_in[1];
    const float* Wm     = (const float*)d_in[2];
    const float* bias   = (const float*)d_in[3];
    float* out = (float*)d_out;

    cudaFuncSetAttribute(kGemmMMA, cudaFuncAttributeMaxDynamicSharedMemorySize, SM_BYTES);

    kFused<<<NBLK_TOTAL, 128>>>(frame, bounds, Wm, bias);
    kScan<<<dim3(128, Bb), 128>>>();
    kGather<<<dim3(Mm, Bb), 128>>>(frame);
    kGemmMMA<<<dim3(Dd / 128, (Bb * Mm) / 128), 256, SM_BYTES>>>(out);
}

// round 13
// speedup vs baseline: 3.3493x; 1.0428x over previous
#include <cuda_runtime.h>
#include <cuda_fp16.h>
#include <math.h>
#include <stdint.h>

#define Bb 8
#define Tt 8192
#define Dd 512
#define Mm 512
#define PD 32
#define LC 16
#define NC (Tt / LC)      // 512

// ---- scratch (device globals; no allocation allowed) ----
__device__ float g_chunkSum[Bb * NC * Dd];            // 8 MB
__device__ float g_chunkPre[Bb * NC * Dd];            // 8 MB
__device__ float g_fine[Bb * NC * 3 * Dd];            // 24 MB: cumulative 4/8/12-row partials
__device__ float g_ffb[Mm * Dd];                      // ff @ W2 + bias (fp32, batch-independent)
__device__ int   g_s[Bb * Mm];
__device__ int   g_e[Bb * Mm];
__device__ __half g_Xh[Bb * Mm * Dd];                 // fp16(X)
__device__ __half g_WhT[Dd * Dd];                     // W1^T [n][k], fp16 hi
__device__ __half g_WlT[Dd * Dd];                     // W1^T [n][k], fp16 lo (W - Wh)

// ================ kFused: 1D grid of 128-thread blocks ================
#define NBLK_CHUNK (NC * Bb)                 // 4096
#define NBLK_BND   32
#define NBLK_FFB   (Mm * 4)                  // 2048
#define NBLK_W     (Dd * 4)                  // 2048
#define NBLK_TOTAL (NBLK_CHUNK + NBLK_BND + NBLK_FFB + NBLK_W)

__global__ void __launch_bounds__(128) kFused(const float* __restrict__ frame,
                                              const void* __restrict__ bounds,
                                              const float* __restrict__ W,
                                              const float* __restrict__ bias) {
    int bid = blockIdx.x, tid = threadIdx.x;

    if (bid < NBLK_CHUNK) {
        int c = bid & (NC - 1), b = bid >> 9, t4 = tid;
        const float4* f = (const float4*)frame;
        float4* fine = (float4*)g_fine;
        float4 acc = make_float4(0.f, 0.f, 0.f, 0.f);
        int base = (b * Tt + c * LC) * (Dd / 4) + t4;
        size_t fbase = ((size_t)(b * NC + c) * 3) * (Dd / 4) + t4;
        #pragma unroll
        for (int r = 0; r < LC; r++) {
            float4 v = f[base + r * (Dd / 4)];
            acc.x += v.x; acc.y += v.y; acc.z += v.z; acc.w += v.w;
            if (r == 3)  fine[fbase + 0 * (Dd / 4)] = acc;
            if (r == 7)  fine[fbase + 1 * (Dd / 4)] = acc;
            if (r == 11) fine[fbase + 2 * (Dd / 4)] = acc;
        }
        ((float4*)g_chunkSum)[(b * NC + c) * (Dd / 4) + t4] = acc;
        return;
    }
    bid -= NBLK_CHUNK;

    if (bid < NBLK_BND) {
        __shared__ int flag;
        if (tid == 0) flag = 0;
        __syncthreads();
        {
            const int* w = (const int*)bounds;
            if (w[2 * tid + 1] != 0) flag = 1;   // benign race
        }
        __syncthreads();
        bool isI64 = (flag == 0);
        int idx = bid * 128 + tid;               // 0..4095
        int b = idx >> 9, m = idx & 511;
        long long sv, ev;
        if (isI64) {
            const long long* p = (const long long*)bounds;
            sv = p[((long long)b * Mm + m) * 2];
            ev = p[((long long)b * Mm + m) * 2 + 1];
        } else {
            const int* p = (const int*)bounds;
            sv = p[(b * Mm + m) * 2];
            ev = p[(b * Mm + m) * 2 + 1];
        }
        long long s = sv; if (s < 0) s = 0; if (s > Tt - 1) s = Tt - 1;
        long long e = ev; if (e > Tt) e = Tt; if (e < s + 1) e = s + 1;
        g_s[b * Mm + m] = (int)s;
        g_e[b * Mm + m] = (int)e;
        return;
    }
    bid -= NBLK_BND;

    if (bid < NBLK_FFB) {
        int m = bid >> 2, q = bid & 3;
        int n = q * 128 + tid;
        __shared__ float ffs[PD];
        if (tid < PD / 2) {
            double pos = (double)m / (double)(Mm - 1);
            double f = exp(log(1000.0) * (double)tid / (double)(PD / 2 - 1));
            double a = pos * f;
            ffs[tid] = (float)sin(a);
            ffs[PD / 2 + tid] = (float)cos(a);
        }
        __syncthreads();
        float acc = bias[n];
        #pragma unroll
        for (int j = 0; j < PD; j++)
            acc = fmaf(ffs[j], W[(Dd + j) * Dd + n], acc);
        g_ffb[m * Dd + n] = acc;
        return;
    }
    bid -= NBLK_FFB;

    {
        int k = bid >> 2, q = bid & 3;
        int n = q * 128 + tid;
        float v = W[k * Dd + n];
        __half h = __float2half_rn(v);
        g_WhT[n * Dd + k] = h;
        g_WlT[n * Dd + k] = __float2half_rn(v - __half2float(h));
    }
}

// ---------------- kScan: exclusive prefix over NC chunks (4 warps/block) ----------------
__global__ void __launch_bounds__(128) kScan() {
    int d4 = blockIdx.x, b = blockIdx.y;
    int tid = threadIdx.x, wid = tid >> 5, lane = tid & 31;
    __shared__ float4 wtot[4];

    const float4* cs = (const float4*)g_chunkSum;
    float4* cp = (float4*)g_chunkPre;
    const int CPL = 4;
    int cbase = (wid * 32 + lane) * CPL;

    float4 v[CPL];
    float4 s = make_float4(0.f, 0.f, 0.f, 0.f);
    #pragma unroll
    for (int j = 0; j < CPL; j++) {
        v[j] = cs[(b * NC + cbase + j) * (Dd / 4) + d4];
        s.x += v[j].x; s.y += v[j].y; s.z += v[j].z; s.w += v[j].w;
    }
    float4 incl = s;
    #pragma unroll
    for (int off = 1; off < 32; off <<= 1) {
        float nx = __shfl_up_sync(0xffffffffu, incl.x, off);
        float ny = __shfl_up_sync(0xffffffffu, incl.y, off);
        float nz = __shfl_up_sync(0xffffffffu, incl.z, off);
        float nw = __shfl_up_sync(0xffffffffu, incl.w, off);
        if (lane >= off) { incl.x += nx; incl.y += ny; incl.z += nz; incl.w += nw; }
    }
    if (lane == 31) wtot[wid] = incl;
    __syncthreads();
    float4 wpre = make_float4(0.f, 0.f, 0.f, 0.f);
    #pragma unroll
    for (int w = 0; w < 4; w++) {
        if (w < wid) {
            float4 t = wtot[w];
            wpre.x += t.x; wpre.y += t.y; wpre.z += t.z; wpre.w += t.w;
        }
    }
    float4 run = make_float4(wpre.x + incl.x - s.x, wpre.y + incl.y - s.y,
                             wpre.z + incl.z - s.z, wpre.w + incl.w - s.w);
    #pragma unroll
    for (int j = 0; j < CPL; j++) {
        cp[(b * NC + cbase + j) * (Dd / 4) + d4] = run;
        run.x += v[j].x; run.y += v[j].y; run.z += v[j].z; run.w += v[j].w;
    }
}

// ---------------- kGather: segment means -> fp16 (2-level prefix) ----------------
__global__ void __launch_bounds__(128) kGather(const float* __restrict__ frame) {
    int m = blockIdx.x, b = blockIdx.y, t4 = threadIdx.x;
    int idx = b * Mm + m;
    int s = g_s[idx], e = g_e[idx];
    int csk = s >> 4;
    int cek = e >> 4; if (cek > NC - 1) cek = NC - 1;

    const float4* f  = (const float4*)frame;
    const float4* cp = (const float4*)g_chunkPre;
    const float4* fine = (const float4*)g_fine;

    float4 accs = cp[(b * NC + csk) * (Dd / 4) + t4];
    int fs = (s - csk * LC) >> 2;
    if (fs > 0) {
        float4 fv = fine[((size_t)(b * NC + csk) * 3 + (fs - 1)) * (Dd / 4) + t4];
        accs.x += fv.x; accs.y += fv.y; accs.z += fv.z; accs.w += fv.w;
    }
    for (int t = csk * LC + 4 * fs; t < s; t++) {
        float4 v = f[(b * Tt + t) * (Dd / 4) + t4];
        accs.x += v.x; accs.y += v.y; accs.z += v.z; accs.w += v.w;
    }
    float4 acce = cp[(b * NC + cek) * (Dd / 4) + t4];
    int de = e - cek * LC;
    int fe = de >> 2; if (fe > 3) fe = 3;
    if (fe > 0) {
        float4 fv = fine[((size_t)(b * NC + cek) * 3 + (fe - 1)) * (Dd / 4) + t4];
        acce.x += fv.x; acce.y += fv.y; acce.z += fv.z; acce.w += fv.w;
    }
    for (int t = cek * LC + 4 * fe; t < e; t++) {
        float4 v = f[(b * Tt + t) * (Dd / 4) + t4];
        acce.x += v.x; acce.y += v.y; acce.z += v.z; acce.w += v.w;
    }

    float inv = 1.f / (float)(e - s);
    __half2 p0 = __floats2half2_rn((acce.x - accs.x) * inv, (acce.y - accs.y) * inv);
    __half2 p1 = __floats2half2_rn((acce.z - accs.z) * inv, (acce.w - accs.w) * inv);
    uint2 hh;
    hh.x = *(uint32_t*)&p0;
    hh.y = *(uint32_t*)&p1;
    *(uint2*)(g_Xh + (size_t)idx * Dd + 4 * t4) = hh;
}

// ================= mma.sync fp16 2-term GEMM, K=512, cp.async 4-stage, 16 warps =================
// out[4096,512] = Xh @ (Wh + Wl) + ffb.
// CTA tile 128(m) x 128(n), KT=32. 16 warps = 4(m) x 4(n); warp tile 32x32.

#define KT 32
#define SROW 40                              // padded row stride (fp16 elems); 80 B
#define TILE_E (128 * SROW)                  // 5120 fp16 per tile
#define TILE_B (TILE_E * 2)                  // 10240 B
#define STAGE_B (3 * TILE_B)                 // A, Bh, Bl  = 30720 B
#define NSTAGES 4
#define SM_BYTES (NSTAGES * STAGE_B)         // 122880 B

static __device__ __forceinline__ uint32_t smem_u32(const void* p) {
    uint32_t a;
    asm("{ .reg .u64 t; cvta.to.shared.u64 t, %1; cvt.u32.u64 %0, t; }" : "=r"(a) : "l"(p));
    return a;
}
static __device__ __forceinline__ void cpasync16(uint32_t saddr, const void* gptr) {
    asm volatile("cp.async.cg.shared.global [%0], [%1], 16;" :: "r"(saddr), "l"(gptr));
}
static __device__ __forceinline__ void cpcommit() {
    asm volatile("cp.async.commit_group;" ::: "memory");
}
template <int N>
static __device__ __forceinline__ void cpwait() {
    asm volatile("cp.async.wait_group %0;" :: "n"(N) : "memory");
}
static __device__ __forceinline__ void ldsm4(uint32_t addr, uint32_t* r) {
    asm volatile("ldmatrix.sync.aligned.m8n8.x4.shared.b16 {%0,%1,%2,%3}, [%4];"
                 : "=r"(r[0]), "=r"(r[1]), "=r"(r[2]), "=r"(r[3]) : "r"(addr));
}
static __device__ __forceinline__ void mma16816(float* c, const uint32_t* a, uint32_t b0, uint32_t b1) {
    asm volatile(
        "mma.sync.aligned.m16n8k16.row.col.f32.f16.f16.f32 "
        "{%0,%1,%2,%3},{%4,%5,%6,%7},{%8,%9},{%0,%1,%2,%3};"
        : "+f"(c[0]), "+f"(c[1]), "+f"(c[2]), "+f"(c[3])
        : "r"(a[0]), "r"(a[1]), "r"(a[2]), "r"(a[3]), "r"(b0), "r"(b1));
}

__global__ void __launch_bounds__(512, 1)
kGemmMMA(float* __restrict__ out) {
    extern __shared__ __align__(16) char sm[];
    uint32_t sb = smem_u32(sm);
    int tid = threadIdx.x;
    int wid = tid >> 5, lane = tid & 31;
    int n0 = blockIdx.x * 128, m0 = blockIdx.y * 128;
    int wr = wid >> 2, wc = wid & 3;     // warp tile at (wr*32 m, wc*32 n)

    const __half* gA  = g_Xh  + (size_t)m0 * Dd;
    const __half* gBh = g_WhT + (size_t)n0 * Dd;
    const __half* gBl = g_WlT + (size_t)n0 * Dd;

    // loader: 512 16B-chunks per tile; thread tid handles chunk tid of each tile
    const int lrow = tid >> 2, lcq = tid & 3;

    auto load_stage = [&](int st, int k0) {
        uint32_t sbase = sb + st * STAGE_B;
        uint32_t soff = lrow * (SROW * 2) + lcq * 16;
        const __half* ga = gA  + (size_t)lrow * Dd + k0 + lcq * 8;
        const __half* gh = gBh + (size_t)lrow * Dd + k0 + lcq * 8;
        const __half* gl = gBl + (size_t)lrow * Dd + k0 + lcq * 8;
        cpasync16(sbase + soff, ga);
        cpasync16(sbase + TILE_B + soff, gh);
        cpasync16(sbase + 2 * TILE_B + soff, gl);
    };

    float acc[2][4][4];
    #pragma unroll
    for (int i = 0; i < 2; i++)
        #pragma unroll
        for (int j = 0; j < 4; j++)
            #pragma unroll
            for (int q = 0; q < 4; q++) acc[i][j][q] = 0.f;

    // prologue: stages 0..2
    #pragma unroll
    for (int s = 0; s < 3; s++) { load_stage(s, s * KT); cpcommit(); }

    int g = lane >> 3, rIn = lane & 7;
    int aRowOff = wr * 32 + rIn + (g & 1) * 8;
    int aColOff = (g >> 1) * 8;
    int bRowOff = wc * 32 + rIn + (g >> 1) * 8;
    int bColOff = (g & 1) * 8;

    const int NKT = Dd / KT;   // 16
    #pragma unroll 1
    for (int kt = 0; kt < NKT; kt++) {
        cpwait<2>();
        __syncthreads();
        if (kt + 3 < NKT) load_stage((kt + 3) & 3, (kt + 3) * KT);
        cpcommit();

        uint32_t stage = sb + (kt & 3) * STAGE_B;
        #pragma unroll
        for (int ks = 0; ks < KT / 16; ks++) {
            int k16 = ks * 16;
            uint32_t a[2][4], bh[2][4], bl[2][4];
            #pragma unroll
            for (int mt = 0; mt < 2; mt++) {
                uint32_t ad = stage + 2 * ((aRowOff + mt * 16) * SROW + k16 + aColOff);
                ldsm4(ad, a[mt]);
            }
            #pragma unroll
            for (int np = 0; np < 2; np++) {
                uint32_t bd = stage + TILE_B + 2 * ((bRowOff + np * 16) * SROW + k16 + bColOff);
                ldsm4(bd, bh[np]);
                uint32_t bd2 = stage + 2 * TILE_B + 2 * ((bRowOff + np * 16) * SROW + k16 + bColOff);
                ldsm4(bd2, bl[np]);
            }
            #pragma unroll
            for (int mt = 0; mt < 2; mt++) {
                #pragma unroll
                for (int np = 0; np < 2; np++) {
                    #pragma unroll
                    for (int h = 0; h < 2; h++) {
                        int nt = np * 2 + h;
                        mma16816(acc[mt][nt], a[mt], bh[np][2 * h], bh[np][2 * h + 1]);
                        mma16816(acc[mt][nt], a[mt], bl[np][2 * h], bl[np][2 * h + 1]);
                    }
                }
            }
        }
    }

    // epilogue: per-row bias from ffb (rows are b*Mm + m; Mm == 512)
    int erow = lane >> 2, ecol2 = (lane & 3) * 2;
    #pragma unroll
    for (int mt = 0; mt < 2; mt++) {
        #pragma unroll
        for (int nt = 0; nt < 4; nt++) {
            int col = n0 + wc * 32 + nt * 8 + ecol2;
            int r0 = m0 + wr * 32 + mt * 16 + erow;
            int mm0 = r0 & (Mm - 1);
            float2 fb0 = *(const float2*)(g_ffb + mm0 * Dd + col);
            float2 fb1 = *(const float2*)(g_ffb + ((r0 + 8) & (Mm - 1)) * Dd + col);
            float2 v0 = make_float2(acc[mt][nt][0] + fb0.x, acc[mt][nt][1] + fb0.y);
            float2 v1 = make_float2(acc[mt][nt][2] + fb1.x, acc[mt][nt][3] + fb1.y);
            *(float2*)(out + (size_t)r0 * Dd + col) = v0;
            *(float2*)(out + (size_t)(r0 + 8) * Dd + col) = v1;
        }
    }
}

extern "C" void kernel_launch(void* const* d_in, const int* in_sizes, int n_in,
                              void* d_out, int out_size) {
    const float* frame  = (const float*)d_in[0];
    const void*  bounds = d_in[1];
    const float* Wm     = (const float*)d_in[2];
    const float* bias   = (const float*)d_in[3];
    float* out = (float*)d_out;

    cudaFuncSetAttribute(kGemmMMA, cudaFuncAttributeMaxDynamicSharedMemorySize, SM_BYTES);

    kFused<<<NBLK_TOTAL, 128>>>(frame, bounds, Wm, bias);
    kScan<<<dim3(128, Bb), 128>>>();
    kGather<<<dim3(Mm, Bb), 128>>>(frame);
    kGemmMMA<<<dim3(Dd / 128, (Bb * Mm) / 128), 512, SM_BYTES>>>(out);
}